// round 1
// baseline (speedup 1.0000x reference)
#include <cuda_runtime.h>
#include <cstdint>
#include <cstddef>

// Problem constants
#define B_   2
#define S_   2048
#define D_   1024
#define H_   16
#define DH_  64
#define BS_  (B_ * S_)            // 4096
#define QKV_N (3 * D_)            // 3072
#define OUT_ATTN_ELEMS ((size_t)BS_ * D_)           // 4,194,304
#define MASKED_BIAS -10000.0f

// Scratch (allocation-free rule: __device__ globals)
__device__ float g_qkv[BS_ * QKV_N];   // [4096, 3072] : Q | K | V packed
__device__ float g_attn[BS_ * D_];     // [4096, 1024] : pre-proj attn output (merged heads)

// ---------------------------------------------------------------------------
// Generic fp32 SGEMM + bias: C[M,N] = A[M,K] @ B[K,N] + bias[N]
// BM=BN=128, BK=16, 256 threads, 8x8 per thread. M%128==0, N%128==0, K%16==0.
// ---------------------------------------------------------------------------
__global__ __launch_bounds__(256)
void sgemm_bias_kernel(const float* __restrict__ A, const float* __restrict__ B,
                       const float* __restrict__ bias, float* __restrict__ C,
                       int M, int N, int K)
{
    __shared__ float As[16][128];   // transposed: As[k][m]
    __shared__ float Bs[16][128];   // Bs[k][n]

    const int tid  = threadIdx.x;
    const int row0 = blockIdx.y * 128;
    const int col0 = blockIdx.x * 128;

    const int ar = tid >> 2;          // 0..63
    const int ac = (tid & 3) << 2;    // 0,4,8,12
    const int br = tid >> 5;          // 0..7
    const int bc = (tid & 31) << 2;   // 0..124

    const int ty = tid >> 4;          // 0..15 -> rows ty*8..+7
    const int tx = tid & 15;          // 0..15 -> cols tx*8..+7

    float acc[8][8];
#pragma unroll
    for (int i = 0; i < 8; i++)
#pragma unroll
        for (int j = 0; j < 8; j++) acc[i][j] = 0.0f;

    for (int kk = 0; kk < K; kk += 16) {
        // load A tile (128x16) transposed into As
#pragma unroll
        for (int u = 0; u < 2; u++) {
            int r = ar + u * 64;
            float4 t = *reinterpret_cast<const float4*>(
                &A[(size_t)(row0 + r) * K + kk + ac]);
            As[ac + 0][r] = t.x; As[ac + 1][r] = t.y;
            As[ac + 2][r] = t.z; As[ac + 3][r] = t.w;
        }
        // load B tile (16x128)
#pragma unroll
        for (int u = 0; u < 2; u++) {
            int r = br + u * 8;
            *reinterpret_cast<float4*>(&Bs[r][bc]) =
                *reinterpret_cast<const float4*>(&B[(size_t)(kk + r) * N + col0 + bc]);
        }
        __syncthreads();

#pragma unroll
        for (int k = 0; k < 16; k++) {
            float a[8], b[8];
            *reinterpret_cast<float4*>(&a[0]) = *reinterpret_cast<const float4*>(&As[k][ty * 8]);
            *reinterpret_cast<float4*>(&a[4]) = *reinterpret_cast<const float4*>(&As[k][ty * 8 + 4]);
            *reinterpret_cast<float4*>(&b[0]) = *reinterpret_cast<const float4*>(&Bs[k][tx * 8]);
            *reinterpret_cast<float4*>(&b[4]) = *reinterpret_cast<const float4*>(&Bs[k][tx * 8 + 4]);
#pragma unroll
            for (int i = 0; i < 8; i++)
#pragma unroll
                for (int j = 0; j < 8; j++)
                    acc[i][j] += a[i] * b[j];
        }
        __syncthreads();
    }

#pragma unroll
    for (int i = 0; i < 8; i++) {
        int r = row0 + ty * 8 + i;
#pragma unroll
        for (int j = 0; j < 8; j += 4) {
            int c = col0 + tx * 8 + j;
            float4 o;
            o.x = acc[i][j + 0] + bias[c + 0];
            o.y = acc[i][j + 1] + bias[c + 1];
            o.z = acc[i][j + 2] + bias[c + 2];
            o.w = acc[i][j + 3] + bias[c + 3];
            *reinterpret_cast<float4*>(&C[(size_t)r * N + c]) = o;
        }
    }
}

// ---------------------------------------------------------------------------
// Scores: W[bh, q, k] = (Q[bh,q,:] . K[bh,k,:]) / 8, masked (-10000 for k>q).
// Only lower-triangle 128x128 tiles launched (kt <= qt). Q/K read from g_qkv.
// grid: (136 tile-pairs, 32 bh), 256 threads.
// ---------------------------------------------------------------------------
__global__ __launch_bounds__(256)
void scores_kernel(float* __restrict__ W)
{
    __shared__ float Qs[16][128];   // [d][m]
    __shared__ float Ks[16][128];   // [d][n]

    const int tid = threadIdx.x;
    const int bh  = blockIdx.y;            // 0..31
    const int b   = bh >> 4;
    const int h   = bh & 15;

    // map linear pair index -> (qt, kt) with kt <= qt
    int pair = blockIdx.x;
    int qt = (int)((-1.0f + sqrtf(1.0f + 8.0f * (float)pair)) * 0.5f);
    while ((qt + 1) * (qt + 2) / 2 <= pair) ++qt;
    while (qt * (qt + 1) / 2 > pair) --qt;
    const int kt = pair - qt * (qt + 1) / 2;

    const int q0 = qt * 128;
    const int k0 = kt * 128;

    const int lr = tid >> 2;          // 0..63
    const int lc = (tid & 3) << 2;    // 0,4,8,12
    const int ty = tid >> 4;
    const int tx = tid & 15;

    const int qcol0 = h * DH_;          // Q columns in qkv
    const int kcol0 = D_ + h * DH_;     // K columns in qkv
    const size_t qrowbase = (size_t)(b * S_ + q0);
    const size_t krowbase = (size_t)(b * S_ + k0);

    float acc[8][8];
#pragma unroll
    for (int i = 0; i < 8; i++)
#pragma unroll
        for (int j = 0; j < 8; j++) acc[i][j] = 0.0f;

    for (int dc = 0; dc < DH_; dc += 16) {
#pragma unroll
        for (int u = 0; u < 2; u++) {
            int r = lr + u * 64;
            float4 tq = *reinterpret_cast<const float4*>(
                &g_qkv[(qrowbase + r) * QKV_N + qcol0 + dc + lc]);
            Qs[lc + 0][r] = tq.x; Qs[lc + 1][r] = tq.y;
            Qs[lc + 2][r] = tq.z; Qs[lc + 3][r] = tq.w;
            float4 tk = *reinterpret_cast<const float4*>(
                &g_qkv[(krowbase + r) * QKV_N + kcol0 + dc + lc]);
            Ks[lc + 0][r] = tk.x; Ks[lc + 1][r] = tk.y;
            Ks[lc + 2][r] = tk.z; Ks[lc + 3][r] = tk.w;
        }
        __syncthreads();

#pragma unroll
        for (int k = 0; k < 16; k++) {
            float a[8], c[8];
            *reinterpret_cast<float4*>(&a[0]) = *reinterpret_cast<const float4*>(&Qs[k][ty * 8]);
            *reinterpret_cast<float4*>(&a[4]) = *reinterpret_cast<const float4*>(&Qs[k][ty * 8 + 4]);
            *reinterpret_cast<float4*>(&c[0]) = *reinterpret_cast<const float4*>(&Ks[k][tx * 8]);
            *reinterpret_cast<float4*>(&c[4]) = *reinterpret_cast<const float4*>(&Ks[k][tx * 8 + 4]);
#pragma unroll
            for (int i = 0; i < 8; i++)
#pragma unroll
                for (int j = 0; j < 8; j++)
                    acc[i][j] += a[i] * c[j];
        }
        __syncthreads();
    }

    float* Wbh = W + (size_t)bh * S_ * S_;
#pragma unroll
    for (int i = 0; i < 8; i++) {
        int q = q0 + ty * 8 + i;
#pragma unroll
        for (int j = 0; j < 8; j++) {
            int k = k0 + tx * 8 + j;
            float s = acc[i][j] * 0.125f;           // 1/sqrt(64)
            if (k > q) s = MASKED_BIAS;
            Wbh[(size_t)q * S_ + k] = s;
        }
    }
}

// ---------------------------------------------------------------------------
// Softmax in place over each row of W. One block per (bh, q) row.
// Only reads k <= q (masked entries underflow to exactly 0 anyway);
// writes zeros for k > q.
// ---------------------------------------------------------------------------
__global__ __launch_bounds__(256)
void softmax_kernel(float* __restrict__ W)
{
    const int tid = threadIdx.x;
    const int row = blockIdx.x;           // bh*2048 + q
    const int q = row & (S_ - 1);
    const int nvalid = q + 1;
    float* w = W + (size_t)row * S_;

    __shared__ float red[256];

    float v[8];
    float m = -1e30f;
#pragma unroll
    for (int r = 0; r < 8; r++) {
        int k = tid + r * 256;
        v[r] = (k < nvalid) ? w[k] : -1e30f;
        m = fmaxf(m, v[r]);
    }
    red[tid] = m; __syncthreads();
    for (int off = 128; off > 0; off >>= 1) {
        if (tid < off) red[tid] = fmaxf(red[tid], red[tid + off]);
        __syncthreads();
    }
    const float mx = red[0];
    __syncthreads();

    float s = 0.0f;
#pragma unroll
    for (int r = 0; r < 8; r++) {
        int k = tid + r * 256;
        if (k < nvalid) { v[r] = expf(v[r] - mx); s += v[r]; }
    }
    red[tid] = s; __syncthreads();
    for (int off = 128; off > 0; off >>= 1) {
        if (tid < off) red[tid] += red[tid + off];
        __syncthreads();
    }
    const float inv = 1.0f / red[0];

#pragma unroll
    for (int r = 0; r < 8; r++) {
        int k = tid + r * 256;
        w[k] = (k < nvalid) ? v[r] * inv : 0.0f;
    }
}

// ---------------------------------------------------------------------------
// AV: g_attn[b*S+q, h*64+d] = sum_k W[bh,q,k] * V[bh,k,d], k only up to the
// q-tile end (weights beyond are exactly 0). V read from g_qkv (offset 2D).
// grid: (16 q-tiles, 32 bh), 256 threads; each thread 8 rows x 4 cols.
// ---------------------------------------------------------------------------
__global__ __launch_bounds__(256)
void av_kernel(const float* __restrict__ W)
{
    __shared__ float Ws[32][128];   // [k][m]
    __shared__ float Vs[32][64];    // [k][n]

    const int tid = threadIdx.x;
    const int bh  = blockIdx.y;
    const int b   = bh >> 4;
    const int h   = bh & 15;
    const int q0  = blockIdx.x * 128;

    const float* Wbh = W + (size_t)bh * S_ * S_;
    const int vcol0 = 2 * D_ + h * DH_;

    const int wm = tid >> 3;          // 0..31
    const int wc = (tid & 7) << 2;    // 0..28
    const int vr = tid >> 4;          // 0..15
    const int vc = (tid & 15) << 2;   // 0..60
    const int ty = tid >> 4;          // 0..15 -> rows ty*8..+7
    const int tx = tid & 15;          // 0..15 -> cols tx*4..+3

    float acc[8][4];
#pragma unroll
    for (int i = 0; i < 8; i++)
#pragma unroll
        for (int j = 0; j < 4; j++) acc[i][j] = 0.0f;

    const int ntiles = (blockIdx.x + 1) * 4;   // k up to q0+128, in 32-chunks
    for (int t = 0; t < ntiles; t++) {
        const int kc = t * 32;
#pragma unroll
        for (int u = 0; u < 4; u++) {
            int m = wm + u * 32;
            float4 tw = *reinterpret_cast<const float4*>(
                &Wbh[(size_t)(q0 + m) * S_ + kc + wc]);
            Ws[wc + 0][m] = tw.x; Ws[wc + 1][m] = tw.y;
            Ws[wc + 2][m] = tw.z; Ws[wc + 3][m] = tw.w;
        }
#pragma unroll
        for (int u = 0; u < 2; u++) {
            int r = vr + u * 16;
            *reinterpret_cast<float4*>(&Vs[r][vc]) =
                *reinterpret_cast<const float4*>(
                    &g_qkv[(size_t)(b * S_ + kc + r) * QKV_N + vcol0 + vc]);
        }
        __syncthreads();

#pragma unroll
        for (int k = 0; k < 32; k++) {
            float wv[8];
            *reinterpret_cast<float4*>(&wv[0]) = *reinterpret_cast<const float4*>(&Ws[k][ty * 8]);
            *reinterpret_cast<float4*>(&wv[4]) = *reinterpret_cast<const float4*>(&Ws[k][ty * 8 + 4]);
            float4 vv = *reinterpret_cast<const float4*>(&Vs[k][tx * 4]);
#pragma unroll
            for (int i = 0; i < 8; i++) {
                acc[i][0] += wv[i] * vv.x;
                acc[i][1] += wv[i] * vv.y;
                acc[i][2] += wv[i] * vv.z;
                acc[i][3] += wv[i] * vv.w;
            }
        }
        __syncthreads();
    }

#pragma unroll
    for (int i = 0; i < 8; i++) {
        int r = b * S_ + q0 + ty * 8 + i;
        float4 o; o.x = acc[i][0]; o.y = acc[i][1]; o.z = acc[i][2]; o.w = acc[i][3];
        *reinterpret_cast<float4*>(&g_attn[(size_t)r * D_ + h * DH_ + tx * 4]) = o;
    }
}

// ---------------------------------------------------------------------------
extern "C" void kernel_launch(void* const* d_in, const int* in_sizes, int n_in,
                              void* d_out, int out_size)
{
    const float* hs       = (const float*)d_in[0];  // [2,2048,1024]
    const float* c_attn_w = (const float*)d_in[1];  // [1024,3072]
    const float* c_attn_b = (const float*)d_in[2];  // [3072]
    const float* c_proj_w = (const float*)d_in[3];  // [1024,1024]
    const float* c_proj_b = (const float*)d_in[4];  // [1024]

    float* out  = (float*)d_out;
    float* Wout = out + OUT_ATTN_ELEMS;             // attn_weights region

    float *qkv_ptr = nullptr, *attn_ptr = nullptr;
    cudaGetSymbolAddress((void**)&qkv_ptr, g_qkv);
    cudaGetSymbolAddress((void**)&attn_ptr, g_attn);

    // 1) QKV GEMM: [4096,1024] @ [1024,3072] + b -> g_qkv
    sgemm_bias_kernel<<<dim3(QKV_N / 128, BS_ / 128), 256>>>(
        hs, c_attn_w, c_attn_b, qkv_ptr, BS_, QKV_N, D_);

    // 2) Scores (lower-triangle tiles only): 136 pairs x 32 bh
    scores_kernel<<<dim3(136, B_ * H_), 256>>>(Wout);

    // 3) Softmax in place, one block per row
    softmax_kernel<<<B_ * H_ * S_, 256>>>(Wout);

    // 4) AV -> g_attn (merged-head layout)
    av_kernel<<<dim3(S_ / 128, B_ * H_), 256>>>(Wout);

    // 5) Proj GEMM: [4096,1024] @ [1024,1024] + b -> out
    sgemm_bias_kernel<<<dim3(D_ / 128, BS_ / 128), 256>>>(
        attn_ptr, c_proj_w, c_proj_b, out, BS_, D_, D_);
}

// round 3
// speedup vs baseline: 1.3835x; 1.3835x over previous
#include <cuda_runtime.h>
#include <cuda_bf16.h>
#include <cstdint>
#include <cstddef>

// Problem constants
#define B_   2
#define S_   2048
#define D_   1024
#define H_   16
#define DH_  64
#define BS_  (B_ * S_)            // 4096
#define QKV_N (3 * D_)            // 3072
#define OUT_ATTN_ELEMS ((size_t)BS_ * D_)           // 4,194,304
#define MASKED_BIAS -10000.0f

// Scratch (allocation-free rule: __device__ globals)
__device__ float g_qkv[BS_ * QKV_N];   // [4096, 3072] : Q | K | V packed (fp32)
__device__ float g_attn[BS_ * D_];     // [4096, 1024] : pre-proj attn output
// bf16 split operands
__device__ __nv_bfloat16 g_ahi[BS_ * D_];
__device__ __nv_bfloat16 g_alo[BS_ * D_];
__device__ __nv_bfloat16 g_w1hi[QKV_N * D_];   // c_attn_w^T [3072,1024]
__device__ __nv_bfloat16 g_w1lo[QKV_N * D_];
__device__ __nv_bfloat16 g_w2hi[D_ * D_];      // c_proj_w^T [1024,1024]
__device__ __nv_bfloat16 g_w2lo[D_ * D_];

// ===========================================================================
// HMMA helpers (mma.sync, legal on base sm_103 target)
// ===========================================================================
__device__ __forceinline__ uint32_t smem_u32(const void* p) {
    uint32_t a;
    asm("{ .reg .u64 t; cvta.to.shared.u64 t, %1; cvt.u32.u64 %0, t; }"
        : "=r"(a) : "l"(p));
    return a;
}

__device__ __forceinline__ void ldm_x4(uint32_t r[4], uint32_t saddr) {
    asm volatile("ldmatrix.sync.aligned.m8n8.x4.shared.b16 {%0,%1,%2,%3}, [%4];"
                 : "=r"(r[0]), "=r"(r[1]), "=r"(r[2]), "=r"(r[3]) : "r"(saddr));
}

__device__ __forceinline__ void mma_bf16(float c[4], const uint32_t a[4],
                                         const uint32_t b[2]) {
    asm volatile(
        "mma.sync.aligned.m16n8k16.row.col.f32.bf16.bf16.f32 "
        "{%0,%1,%2,%3}, {%4,%5,%6,%7}, {%8,%9}, {%0,%1,%2,%3};"
        : "+f"(c[0]), "+f"(c[1]), "+f"(c[2]), "+f"(c[3])
        : "r"(a[0]), "r"(a[1]), "r"(a[2]), "r"(a[3]), "r"(b[0]), "r"(b[1]));
}

// ===========================================================================
// Split kernels: fp32 -> bf16 hi/lo
// ===========================================================================
__global__ __launch_bounds__(256)
void split_rows_kernel(const float* __restrict__ in,
                       __nv_bfloat16* __restrict__ hi,
                       __nv_bfloat16* __restrict__ lo, int n4)
{
    int i = blockIdx.x * 256 + threadIdx.x;
    if (i >= n4) return;
    float4 v = reinterpret_cast<const float4*>(in)[i];
    __nv_bfloat16 h0 = __float2bfloat16(v.x);
    __nv_bfloat16 h1 = __float2bfloat16(v.y);
    __nv_bfloat16 h2 = __float2bfloat16(v.z);
    __nv_bfloat16 h3 = __float2bfloat16(v.w);
    __nv_bfloat16 l0 = __float2bfloat16(v.x - __bfloat162float(h0));
    __nv_bfloat16 l1 = __float2bfloat16(v.y - __bfloat162float(h1));
    __nv_bfloat16 l2 = __float2bfloat16(v.z - __bfloat162float(h2));
    __nv_bfloat16 l3 = __float2bfloat16(v.w - __bfloat162float(h3));
    __nv_bfloat162 hh0; hh0.x = h0; hh0.y = h1;
    __nv_bfloat162 hh1; hh1.x = h2; hh1.y = h3;
    __nv_bfloat162 ll0; ll0.x = l0; ll0.y = l1;
    __nv_bfloat162 ll1; ll1.x = l2; ll1.y = l3;
    reinterpret_cast<__nv_bfloat162*>(hi)[i * 2 + 0] = hh0;
    reinterpret_cast<__nv_bfloat162*>(hi)[i * 2 + 1] = hh1;
    reinterpret_cast<__nv_bfloat162*>(lo)[i * 2 + 0] = ll0;
    reinterpret_cast<__nv_bfloat162*>(lo)[i * 2 + 1] = ll1;
}

// Transpose + split: in [K,N] fp32 -> out [N,K] bf16 hi/lo
__global__ __launch_bounds__(256)
void split_T_kernel(const float* __restrict__ in,
                    __nv_bfloat16* __restrict__ hi,
                    __nv_bfloat16* __restrict__ lo, int K, int N)
{
    __shared__ float t[32][33];
    int n0 = blockIdx.x * 32, k0 = blockIdx.y * 32;
    int tx = threadIdx.x & 31, ty = threadIdx.x >> 5;   // 32 x 8
#pragma unroll
    for (int i = 0; i < 4; i++)
        t[ty + 8 * i][tx] = in[(size_t)(k0 + ty + 8 * i) * N + n0 + tx];
    __syncthreads();
#pragma unroll
    for (int i = 0; i < 4; i++) {
        float v = t[tx][ty + 8 * i];
        __nv_bfloat16 h = __float2bfloat16(v);
        __nv_bfloat16 l = __float2bfloat16(v - __bfloat162float(h));
        size_t o = (size_t)(n0 + ty + 8 * i) * K + k0 + tx;
        hi[o] = h;
        lo[o] = l;
    }
}

// ===========================================================================
// HMMA GEMM: C[M,N] = (Ahi+Alo)[M,K] @ (Bhi+Blo)[N,K]^T + bias[N]
// 128x128 CTA tile, BK=32, 8 warps (4m x 2n), warp tile 32x64.
// 3 bf16 passes: hi*hi + hi*lo + lo*hi (fp32 accum).
// ===========================================================================
#define SPAD 40   // smem row stride in elements (32 + 8 pad) -> conflict-free ldmatrix

__global__ __launch_bounds__(256)
void gemm_hmma_kernel(const __nv_bfloat16* __restrict__ Ahi,
                      const __nv_bfloat16* __restrict__ Alo,
                      const __nv_bfloat16* __restrict__ Bhi,
                      const __nv_bfloat16* __restrict__ Blo,
                      const float* __restrict__ bias,
                      float* __restrict__ C, int M, int N, int K)
{
    __shared__ __nv_bfloat16 sA[2][128 * SPAD];   // [hi/lo][row][k]
    __shared__ __nv_bfloat16 sB[2][128 * SPAD];   // [hi/lo][n][k]

    const int tid  = threadIdx.x;
    const int lane = tid & 31;
    const int warp = tid >> 5;
    const int row0 = blockIdx.y * 128;
    const int col0 = blockIdx.x * 128;
    const int warp_m = (warp & 3) * 32;   // 4 warps along M
    const int warp_n = (warp >> 2) * 64;  // 2 warps along N

    float acc[2][8][4];
#pragma unroll
    for (int i = 0; i < 2; i++)
#pragma unroll
        for (int j = 0; j < 8; j++)
#pragma unroll
            for (int r = 0; r < 4; r++) acc[i][j][r] = 0.0f;

    // Precompute ldmatrix shared addresses (per-lane), element indices
    // A frag tile i (m16): rows warp_m + i*16 + (lane%16), col ks + (lane/16)*8
    const int a_r = warp_m + (lane & 15);
    const int a_c = (lane >> 4) * 8;
    // B frag pair jj: rows warp_n + jj*16 + (lane%8) + (lane/16)*8, col ks + ((lane>>3)&1)*8
    const int b_r = warp_n + (lane & 7) + (lane >> 4) * 8;
    const int b_c = ((lane >> 3) & 1) * 8;

    for (int kk = 0; kk < K; kk += 32) {
        // --- load 4 tiles (Ahi, Alo, Bhi, Blo), each 128x32 bf16 ---
#pragma unroll
        for (int u = 0; u < 2; u++) {
            int s   = tid + u * 256;        // 0..511
            int r   = s >> 2;               // 0..127
            int cg  = (s & 3) * 8;          // 0,8,16,24
            size_t goffA = (size_t)(row0 + r) * K + kk + cg;
            size_t goffB = (size_t)(col0 + r) * K + kk + cg;
            int soff = r * SPAD + cg;
            *reinterpret_cast<uint4*>(&sA[0][soff]) =
                *reinterpret_cast<const uint4*>(Ahi + goffA);
            *reinterpret_cast<uint4*>(&sA[1][soff]) =
                *reinterpret_cast<const uint4*>(Alo + goffA);
            *reinterpret_cast<uint4*>(&sB[0][soff]) =
                *reinterpret_cast<const uint4*>(Bhi + goffB);
            *reinterpret_cast<uint4*>(&sB[1][soff]) =
                *reinterpret_cast<const uint4*>(Blo + goffB);
        }
        __syncthreads();

        // --- compute: 2 k16 steps x 3 passes ---
#pragma unroll
        for (int ks = 0; ks < 32; ks += 16) {
            uint32_t a_h[2][4], a_l[2][4];
            uint32_t b_h[8][2], b_l[8][2];
#pragma unroll
            for (int i = 0; i < 2; i++) {
                int el = (a_r + i * 16) * SPAD + ks + a_c;
                ldm_x4(a_h[i], smem_u32(&sA[0][el]));
                ldm_x4(a_l[i], smem_u32(&sA[1][el]));
            }
#pragma unroll
            for (int jj = 0; jj < 4; jj++) {
                int el = (b_r + jj * 16) * SPAD + ks + b_c;
                ldm_x4(&b_h[jj * 2][0], smem_u32(&sB[0][el]));
                ldm_x4(&b_l[jj * 2][0], smem_u32(&sB[1][el]));
            }
#pragma unroll
            for (int i = 0; i < 2; i++)
#pragma unroll
                for (int j = 0; j < 8; j++) {
                    mma_bf16(acc[i][j], a_h[i], b_h[j]);
                    mma_bf16(acc[i][j], a_h[i], b_l[j]);
                    mma_bf16(acc[i][j], a_l[i], b_h[j]);
                }
        }
        __syncthreads();
    }

    // --- epilogue: C = acc + bias ---
#pragma unroll
    for (int i = 0; i < 2; i++) {
#pragma unroll
        for (int j = 0; j < 8; j++) {
            int m = row0 + warp_m + i * 16 + (lane >> 2);
            int n = col0 + warp_n + j * 8 + (lane & 3) * 2;
            float2 bz = *reinterpret_cast<const float2*>(&bias[n]);
            float2 o0; o0.x = acc[i][j][0] + bz.x; o0.y = acc[i][j][1] + bz.y;
            float2 o1; o1.x = acc[i][j][2] + bz.x; o1.y = acc[i][j][3] + bz.y;
            *reinterpret_cast<float2*>(&C[(size_t)m * N + n]) = o0;
            *reinterpret_cast<float2*>(&C[(size_t)(m + 8) * N + n]) = o1;
        }
    }
}

// ---------------------------------------------------------------------------
// Scores: W[bh, q, k] = (Q . K) / 8, masked. Lower-triangle tiles only.
// ---------------------------------------------------------------------------
__global__ __launch_bounds__(256)
void scores_kernel(float* __restrict__ W)
{
    __shared__ float Qs[16][128];
    __shared__ float Ks[16][128];

    const int tid = threadIdx.x;
    const int bh  = blockIdx.y;
    const int b   = bh >> 4;
    const int h   = bh & 15;

    int pair = blockIdx.x;
    int qt = (int)((-1.0f + sqrtf(1.0f + 8.0f * (float)pair)) * 0.5f);
    while ((qt + 1) * (qt + 2) / 2 <= pair) ++qt;
    while (qt * (qt + 1) / 2 > pair) --qt;
    const int kt = pair - qt * (qt + 1) / 2;

    const int q0 = qt * 128;
    const int k0 = kt * 128;

    const int lr = tid >> 2;
    const int lc = (tid & 3) << 2;
    const int ty = tid >> 4;
    const int tx = tid & 15;

    const int qcol0 = h * DH_;
    const int kcol0 = D_ + h * DH_;
    const size_t qrowbase = (size_t)(b * S_ + q0);
    const size_t krowbase = (size_t)(b * S_ + k0);

    float acc[8][8];
#pragma unroll
    for (int i = 0; i < 8; i++)
#pragma unroll
        for (int j = 0; j < 8; j++) acc[i][j] = 0.0f;

    for (int dc = 0; dc < DH_; dc += 16) {
#pragma unroll
        for (int u = 0; u < 2; u++) {
            int r = lr + u * 64;
            float4 tq = *reinterpret_cast<const float4*>(
                &g_qkv[(qrowbase + r) * QKV_N + qcol0 + dc + lc]);
            Qs[lc + 0][r] = tq.x; Qs[lc + 1][r] = tq.y;
            Qs[lc + 2][r] = tq.z; Qs[lc + 3][r] = tq.w;
            float4 tk = *reinterpret_cast<const float4*>(
                &g_qkv[(krowbase + r) * QKV_N + kcol0 + dc + lc]);
            Ks[lc + 0][r] = tk.x; Ks[lc + 1][r] = tk.y;
            Ks[lc + 2][r] = tk.z; Ks[lc + 3][r] = tk.w;
        }
        __syncthreads();

#pragma unroll
        for (int k = 0; k < 16; k++) {
            float a[8], c[8];
            *reinterpret_cast<float4*>(&a[0]) = *reinterpret_cast<const float4*>(&Qs[k][ty * 8]);
            *reinterpret_cast<float4*>(&a[4]) = *reinterpret_cast<const float4*>(&Qs[k][ty * 8 + 4]);
            *reinterpret_cast<float4*>(&c[0]) = *reinterpret_cast<const float4*>(&Ks[k][tx * 8]);
            *reinterpret_cast<float4*>(&c[4]) = *reinterpret_cast<const float4*>(&Ks[k][tx * 8 + 4]);
#pragma unroll
            for (int i = 0; i < 8; i++)
#pragma unroll
                for (int j = 0; j < 8; j++)
                    acc[i][j] += a[i] * c[j];
        }
        __syncthreads();
    }

    float* Wbh = W + (size_t)bh * S_ * S_;
#pragma unroll
    for (int i = 0; i < 8; i++) {
        int q = q0 + ty * 8 + i;
#pragma unroll
        for (int j = 0; j < 8; j++) {
            int k = k0 + tx * 8 + j;
            float s = acc[i][j] * 0.125f;
            if (k > q) s = MASKED_BIAS;
            Wbh[(size_t)q * S_ + k] = s;
        }
    }
}

// ---------------------------------------------------------------------------
// Softmax in place over each row of W.
// ---------------------------------------------------------------------------
__global__ __launch_bounds__(256)
void softmax_kernel(float* __restrict__ W)
{
    const int tid = threadIdx.x;
    const int row = blockIdx.x;
    const int q = row & (S_ - 1);
    const int nvalid = q + 1;
    float* w = W + (size_t)row * S_;

    __shared__ float red[256];

    float v[8];
    float m = -1e30f;
#pragma unroll
    for (int r = 0; r < 8; r++) {
        int k = tid + r * 256;
        v[r] = (k < nvalid) ? w[k] : -1e30f;
        m = fmaxf(m, v[r]);
    }
    red[tid] = m; __syncthreads();
    for (int off = 128; off > 0; off >>= 1) {
        if (tid < off) red[tid] = fmaxf(red[tid], red[tid + off]);
        __syncthreads();
    }
    const float mx = red[0];
    __syncthreads();

    float s = 0.0f;
#pragma unroll
    for (int r = 0; r < 8; r++) {
        int k = tid + r * 256;
        if (k < nvalid) { v[r] = expf(v[r] - mx); s += v[r]; }
    }
    red[tid] = s; __syncthreads();
    for (int off = 128; off > 0; off >>= 1) {
        if (tid < off) red[tid] += red[tid + off];
        __syncthreads();
    }
    const float inv = 1.0f / red[0];

#pragma unroll
    for (int r = 0; r < 8; r++) {
        int k = tid + r * 256;
        w[k] = (k < nvalid) ? v[r] * inv : 0.0f;
    }
}

// ---------------------------------------------------------------------------
// AV: g_attn = softmax(W) @ V, causal k-range.
// ---------------------------------------------------------------------------
__global__ __launch_bounds__(256)
void av_kernel(const float* __restrict__ W)
{
    __shared__ float Ws[32][128];
    __shared__ float Vs[32][64];

    const int tid = threadIdx.x;
    const int bh  = blockIdx.y;
    const int b   = bh >> 4;
    const int h   = bh & 15;
    const int q0  = blockIdx.x * 128;

    const float* Wbh = W + (size_t)bh * S_ * S_;
    const int vcol0 = 2 * D_ + h * DH_;

    const int wm = tid >> 3;
    const int wc = (tid & 7) << 2;
    const int vr = tid >> 4;
    const int vc = (tid & 15) << 2;
    const int ty = tid >> 4;
    const int tx = tid & 15;

    float acc[8][4];
#pragma unroll
    for (int i = 0; i < 8; i++)
#pragma unroll
        for (int j = 0; j < 4; j++) acc[i][j] = 0.0f;

    const int ntiles = (blockIdx.x + 1) * 4;
    for (int t = 0; t < ntiles; t++) {
        const int kc = t * 32;
#pragma unroll
        for (int u = 0; u < 4; u++) {
            int m = wm + u * 32;
            float4 tw = *reinterpret_cast<const float4*>(
                &Wbh[(size_t)(q0 + m) * S_ + kc + wc]);
            Ws[wc + 0][m] = tw.x; Ws[wc + 1][m] = tw.y;
            Ws[wc + 2][m] = tw.z; Ws[wc + 3][m] = tw.w;
        }
#pragma unroll
        for (int u = 0; u < 2; u++) {
            int r = vr + u * 16;
            *reinterpret_cast<float4*>(&Vs[r][vc]) =
                *reinterpret_cast<const float4*>(
                    &g_qkv[(size_t)(b * S_ + kc + r) * QKV_N + vcol0 + vc]);
        }
        __syncthreads();

#pragma unroll
        for (int k = 0; k < 32; k++) {
            float wv[8];
            *reinterpret_cast<float4*>(&wv[0]) = *reinterpret_cast<const float4*>(&Ws[k][ty * 8]);
            *reinterpret_cast<float4*>(&wv[4]) = *reinterpret_cast<const float4*>(&Ws[k][ty * 8 + 4]);
            float4 vv = *reinterpret_cast<const float4*>(&Vs[k][tx * 4]);
#pragma unroll
            for (int i = 0; i < 8; i++) {
                acc[i][0] += wv[i] * vv.x;
                acc[i][1] += wv[i] * vv.y;
                acc[i][2] += wv[i] * vv.z;
                acc[i][3] += wv[i] * vv.w;
            }
        }
        __syncthreads();
    }

#pragma unroll
    for (int i = 0; i < 8; i++) {
        int r = b * S_ + q0 + ty * 8 + i;
        float4 o; o.x = acc[i][0]; o.y = acc[i][1]; o.z = acc[i][2]; o.w = acc[i][3];
        *reinterpret_cast<float4*>(&g_attn[(size_t)r * D_ + h * DH_ + tx * 4]) = o;
    }
}

// ---------------------------------------------------------------------------
extern "C" void kernel_launch(void* const* d_in, const int* in_sizes, int n_in,
                              void* d_out, int out_size)
{
    const float* hs       = (const float*)d_in[0];  // [2,2048,1024]
    const float* c_attn_w = (const float*)d_in[1];  // [1024,3072]
    const float* c_attn_b = (const float*)d_in[2];  // [3072]
    const float* c_proj_w = (const float*)d_in[3];  // [1024,1024]
    const float* c_proj_b = (const float*)d_in[4];  // [1024]

    float* out  = (float*)d_out;
    float* Wout = out + OUT_ATTN_ELEMS;

    float *qkv_ptr = nullptr, *attn_ptr = nullptr;
    __nv_bfloat16 *ahi, *alo, *w1hi, *w1lo, *w2hi, *w2lo;
    cudaGetSymbolAddress((void**)&qkv_ptr, g_qkv);
    cudaGetSymbolAddress((void**)&attn_ptr, g_attn);
    cudaGetSymbolAddress((void**)&ahi,  g_ahi);
    cudaGetSymbolAddress((void**)&alo,  g_alo);
    cudaGetSymbolAddress((void**)&w1hi, g_w1hi);
    cudaGetSymbolAddress((void**)&w1lo, g_w1lo);
    cudaGetSymbolAddress((void**)&w2hi, g_w2hi);
    cudaGetSymbolAddress((void**)&w2lo, g_w2lo);

    // 0a) split hidden_states -> bf16 hi/lo
    split_rows_kernel<<<(BS_ * D_ / 4 + 255) / 256, 256>>>(hs, ahi, alo, BS_ * D_ / 4);
    // 0b) transpose+split weights
    split_T_kernel<<<dim3(QKV_N / 32, D_ / 32), 256>>>(c_attn_w, w1hi, w1lo, D_, QKV_N);
    split_T_kernel<<<dim3(D_ / 32, D_ / 32), 256>>>(c_proj_w, w2hi, w2lo, D_, D_);

    // 1) QKV GEMM on tensor cores (HMMA): [4096,1024] @ [1024,3072] + b -> g_qkv
    gemm_hmma_kernel<<<dim3(QKV_N / 128, BS_ / 128), 256>>>(
        ahi, alo, w1hi, w1lo, c_attn_b, qkv_ptr, BS_, QKV_N, D_);

    // 2) Scores (lower-triangle tiles only)
    scores_kernel<<<dim3(136, B_ * H_), 256>>>(Wout);

    // 3) Softmax in place
    softmax_kernel<<<B_ * H_ * S_, 256>>>(Wout);

    // 4) AV -> g_attn
    av_kernel<<<dim3(S_ / 128, B_ * H_), 256>>>(Wout);

    // 5) split attn output, then proj GEMM (HMMA)
    split_rows_kernel<<<(BS_ * D_ / 4 + 255) / 256, 256>>>(attn_ptr, ahi, alo, BS_ * D_ / 4);
    gemm_hmma_kernel<<<dim3(D_ / 128, BS_ / 128), 256>>>(
        ahi, alo, w2hi, w2lo, c_proj_b, out, BS_, D_, D_);
}

// round 4
// speedup vs baseline: 1.8686x; 1.3507x over previous
#include <cuda_runtime.h>
#include <cuda_bf16.h>
#include <cstdint>
#include <cstddef>

// Problem constants
#define B_   2
#define S_   2048
#define D_   1024
#define H_   16
#define DH_  64
#define BS_  (B_ * S_)            // 4096
#define QKV_N (3 * D_)            // 3072
#define OUT_ATTN_ELEMS ((size_t)BS_ * D_)           // 4,194,304
#define MASKED_BIAS -10000.0f

// Scratch (allocation-free rule: __device__ globals)
__device__ float g_qkv[BS_ * QKV_N];   // [4096, 3072] : Q | K | V packed (fp32)
__device__ float g_attn[BS_ * D_];     // [4096, 1024] : pre-proj attn output
// bf16 split operands for the dense GEMMs
__device__ __nv_bfloat16 g_ahi[BS_ * D_];
__device__ __nv_bfloat16 g_alo[BS_ * D_];
__device__ __nv_bfloat16 g_w1hi[QKV_N * D_];   // c_attn_w^T [3072,1024]
__device__ __nv_bfloat16 g_w1lo[QKV_N * D_];
__device__ __nv_bfloat16 g_w2hi[D_ * D_];      // c_proj_w^T [1024,1024]
__device__ __nv_bfloat16 g_w2lo[D_ * D_];

// ===========================================================================
// HMMA helpers
// ===========================================================================
__device__ __forceinline__ uint32_t smem_u32(const void* p) {
    uint32_t a;
    asm("{ .reg .u64 t; cvta.to.shared.u64 t, %1; cvt.u32.u64 %0, t; }"
        : "=r"(a) : "l"(p));
    return a;
}

__device__ __forceinline__ void ldm_x4(uint32_t r[4], uint32_t saddr) {
    asm volatile("ldmatrix.sync.aligned.m8n8.x4.shared.b16 {%0,%1,%2,%3}, [%4];"
                 : "=r"(r[0]), "=r"(r[1]), "=r"(r[2]), "=r"(r[3]) : "r"(saddr));
}

__device__ __forceinline__ void mma_bf16(float c[4], const uint32_t a[4],
                                         const uint32_t b[2]) {
    asm volatile(
        "mma.sync.aligned.m16n8k16.row.col.f32.bf16.bf16.f32 "
        "{%0,%1,%2,%3}, {%4,%5,%6,%7}, {%8,%9}, {%0,%1,%2,%3};"
        : "+f"(c[0]), "+f"(c[1]), "+f"(c[2]), "+f"(c[3])
        : "r"(a[0]), "r"(a[1]), "r"(a[2]), "r"(a[3]), "r"(b[0]), "r"(b[1]));
}

// Split a float4 into hi/lo bf16x4, store as 8B each.
__device__ __forceinline__ void split4(float4 v, __nv_bfloat16* hp,
                                       __nv_bfloat16* lp)
{
    __nv_bfloat162 h0, h1, l0, l1;
    h0.x = __float2bfloat16(v.x); h0.y = __float2bfloat16(v.y);
    h1.x = __float2bfloat16(v.z); h1.y = __float2bfloat16(v.w);
    l0.x = __float2bfloat16(v.x - __bfloat162float(h0.x));
    l0.y = __float2bfloat16(v.y - __bfloat162float(h0.y));
    l1.x = __float2bfloat16(v.z - __bfloat162float(h1.x));
    l1.y = __float2bfloat16(v.w - __bfloat162float(h1.y));
    uint2 hu, lu;
    hu.x = *reinterpret_cast<uint32_t*>(&h0);
    hu.y = *reinterpret_cast<uint32_t*>(&h1);
    lu.x = *reinterpret_cast<uint32_t*>(&l0);
    lu.y = *reinterpret_cast<uint32_t*>(&l1);
    *reinterpret_cast<uint2*>(hp) = hu;
    *reinterpret_cast<uint2*>(lp) = lu;
}

// ===========================================================================
// Split kernels: fp32 -> bf16 hi/lo (for dense GEMM operands)
// ===========================================================================
__global__ __launch_bounds__(256)
void split_rows_kernel(const float* __restrict__ in,
                       __nv_bfloat16* __restrict__ hi,
                       __nv_bfloat16* __restrict__ lo, int n4)
{
    int i = blockIdx.x * 256 + threadIdx.x;
    if (i >= n4) return;
    float4 v = reinterpret_cast<const float4*>(in)[i];
    split4(v, hi + i * 4, lo + i * 4);
}

// Transpose + split: in [K,N] fp32 -> out [N,K] bf16 hi/lo
__global__ __launch_bounds__(256)
void split_T_kernel(const float* __restrict__ in,
                    __nv_bfloat16* __restrict__ hi,
                    __nv_bfloat16* __restrict__ lo, int K, int N)
{
    __shared__ float t[32][33];
    int n0 = blockIdx.x * 32, k0 = blockIdx.y * 32;
    int tx = threadIdx.x & 31, ty = threadIdx.x >> 5;   // 32 x 8
#pragma unroll
    for (int i = 0; i < 4; i++)
        t[ty + 8 * i][tx] = in[(size_t)(k0 + ty + 8 * i) * N + n0 + tx];
    __syncthreads();
#pragma unroll
    for (int i = 0; i < 4; i++) {
        float v = t[tx][ty + 8 * i];
        __nv_bfloat16 h = __float2bfloat16(v);
        __nv_bfloat16 l = __float2bfloat16(v - __bfloat162float(h));
        size_t o = (size_t)(n0 + ty + 8 * i) * K + k0 + tx;
        hi[o] = h;
        lo[o] = l;
    }
}

// ===========================================================================
// HMMA GEMM: C[M,N] = (Ahi+Alo)[M,K] @ (Bhi+Blo)[N,K]^T + bias[N]
// 128x128 CTA tile, BK=32, 8 warps (4m x 2n), warp tile 32x64.
// ===========================================================================
#define SPAD 40

__global__ __launch_bounds__(256)
void gemm_hmma_kernel(const __nv_bfloat16* __restrict__ Ahi,
                      const __nv_bfloat16* __restrict__ Alo,
                      const __nv_bfloat16* __restrict__ Bhi,
                      const __nv_bfloat16* __restrict__ Blo,
                      const float* __restrict__ bias,
                      float* __restrict__ C, int M, int N, int K)
{
    __shared__ __nv_bfloat16 sA[2][128 * SPAD];
    __shared__ __nv_bfloat16 sB[2][128 * SPAD];

    const int tid  = threadIdx.x;
    const int lane = tid & 31;
    const int warp = tid >> 5;
    const int row0 = blockIdx.y * 128;
    const int col0 = blockIdx.x * 128;
    const int warp_m = (warp & 3) * 32;
    const int warp_n = (warp >> 2) * 64;

    float acc[2][8][4];
#pragma unroll
    for (int i = 0; i < 2; i++)
#pragma unroll
        for (int j = 0; j < 8; j++)
#pragma unroll
            for (int r = 0; r < 4; r++) acc[i][j][r] = 0.0f;

    const int a_r = warp_m + (lane & 15);
    const int a_c = (lane >> 4) * 8;
    const int b_r = warp_n + (lane & 7) + (lane >> 4) * 8;
    const int b_c = ((lane >> 3) & 1) * 8;

    for (int kk = 0; kk < K; kk += 32) {
#pragma unroll
        for (int u = 0; u < 2; u++) {
            int s   = tid + u * 256;
            int r   = s >> 2;
            int cg  = (s & 3) * 8;
            size_t goffA = (size_t)(row0 + r) * K + kk + cg;
            size_t goffB = (size_t)(col0 + r) * K + kk + cg;
            int soff = r * SPAD + cg;
            *reinterpret_cast<uint4*>(&sA[0][soff]) =
                *reinterpret_cast<const uint4*>(Ahi + goffA);
            *reinterpret_cast<uint4*>(&sA[1][soff]) =
                *reinterpret_cast<const uint4*>(Alo + goffA);
            *reinterpret_cast<uint4*>(&sB[0][soff]) =
                *reinterpret_cast<const uint4*>(Bhi + goffB);
            *reinterpret_cast<uint4*>(&sB[1][soff]) =
                *reinterpret_cast<const uint4*>(Blo + goffB);
        }
        __syncthreads();

#pragma unroll
        for (int ks = 0; ks < 32; ks += 16) {
            uint32_t a_h[2][4], a_l[2][4];
            uint32_t b_h[8][2], b_l[8][2];
#pragma unroll
            for (int i = 0; i < 2; i++) {
                int el = (a_r + i * 16) * SPAD + ks + a_c;
                ldm_x4(a_h[i], smem_u32(&sA[0][el]));
                ldm_x4(a_l[i], smem_u32(&sA[1][el]));
            }
#pragma unroll
            for (int jj = 0; jj < 4; jj++) {
                int el = (b_r + jj * 16) * SPAD + ks + b_c;
                ldm_x4(&b_h[jj * 2][0], smem_u32(&sB[0][el]));
                ldm_x4(&b_l[jj * 2][0], smem_u32(&sB[1][el]));
            }
#pragma unroll
            for (int i = 0; i < 2; i++)
#pragma unroll
                for (int j = 0; j < 8; j++) {
                    mma_bf16(acc[i][j], a_h[i], b_h[j]);
                    mma_bf16(acc[i][j], a_h[i], b_l[j]);
                    mma_bf16(acc[i][j], a_l[i], b_h[j]);
                }
        }
        __syncthreads();
    }

#pragma unroll
    for (int i = 0; i < 2; i++) {
#pragma unroll
        for (int j = 0; j < 8; j++) {
            int m = row0 + warp_m + i * 16 + (lane >> 2);
            int n = col0 + warp_n + j * 8 + (lane & 3) * 2;
            float2 bz = *reinterpret_cast<const float2*>(&bias[n]);
            float2 o0; o0.x = acc[i][j][0] + bz.x; o0.y = acc[i][j][1] + bz.y;
            float2 o1; o1.x = acc[i][j][2] + bz.x; o1.y = acc[i][j][3] + bz.y;
            *reinterpret_cast<float2*>(&C[(size_t)m * N + n]) = o0;
            *reinterpret_cast<float2*>(&C[(size_t)(m + 8) * N + n]) = o1;
        }
    }
}

// ===========================================================================
// Scores on HMMA: W[bh,q,k] = (Q.K)/8, masked. Lower-triangle tiles only.
// In-kernel fp32->bf16 hi/lo split of Q,K (both natural [row][d] layout).
// 128x128 tile, 2 chunks of BK=32 over Dh=64, 8 warps 32x64.
// ===========================================================================
__global__ __launch_bounds__(256)
void scores_hmma_kernel(float* __restrict__ W)
{
    __shared__ __nv_bfloat16 sQ[2][128 * SPAD];
    __shared__ __nv_bfloat16 sK[2][128 * SPAD];

    const int tid  = threadIdx.x;
    const int lane = tid & 31;
    const int warp = tid >> 5;
    const int bh   = blockIdx.y;
    const int b    = bh >> 4;
    const int h    = bh & 15;

    int pair = blockIdx.x;
    int qt = (int)((-1.0f + sqrtf(1.0f + 8.0f * (float)pair)) * 0.5f);
    while ((qt + 1) * (qt + 2) / 2 <= pair) ++qt;
    while (qt * (qt + 1) / 2 > pair) --qt;
    const int kt = pair - qt * (qt + 1) / 2;

    const int q0 = qt * 128;
    const int k0 = kt * 128;
    const int warp_m = (warp & 3) * 32;
    const int warp_n = (warp >> 2) * 64;

    float acc[2][8][4];
#pragma unroll
    for (int i = 0; i < 2; i++)
#pragma unroll
        for (int j = 0; j < 8; j++)
#pragma unroll
            for (int r = 0; r < 4; r++) acc[i][j][r] = 0.0f;

    const int a_r = warp_m + (lane & 15);
    const int a_c = (lane >> 4) * 8;
    const int b_r = warp_n + (lane & 7) + (lane >> 4) * 8;
    const int b_c = ((lane >> 3) & 1) * 8;

    const size_t qbase = (size_t)(b * S_ + q0) * QKV_N + h * DH_;
    const size_t kbase = (size_t)(b * S_ + k0) * QKV_N + D_ + h * DH_;

    const int lr = tid >> 1;            // 0..127
    const int lc0 = (tid & 1) * 16;     // 0 or 16

    for (int dc = 0; dc < DH_; dc += 32) {
#pragma unroll
        for (int i = 0; i < 4; i++) {
            int c = lc0 + i * 4;
            float4 vq = *reinterpret_cast<const float4*>(
                &g_qkv[qbase + (size_t)lr * QKV_N + dc + c]);
            float4 vk = *reinterpret_cast<const float4*>(
                &g_qkv[kbase + (size_t)lr * QKV_N + dc + c]);
            split4(vq, &sQ[0][lr * SPAD + c], &sQ[1][lr * SPAD + c]);
            split4(vk, &sK[0][lr * SPAD + c], &sK[1][lr * SPAD + c]);
        }
        __syncthreads();

#pragma unroll
        for (int ks = 0; ks < 32; ks += 16) {
            uint32_t a_h[2][4], a_l[2][4];
            uint32_t b_h[8][2], b_l[8][2];
#pragma unroll
            for (int i = 0; i < 2; i++) {
                int el = (a_r + i * 16) * SPAD + ks + a_c;
                ldm_x4(a_h[i], smem_u32(&sQ[0][el]));
                ldm_x4(a_l[i], smem_u32(&sQ[1][el]));
            }
#pragma unroll
            for (int jj = 0; jj < 4; jj++) {
                int el = (b_r + jj * 16) * SPAD + ks + b_c;
                ldm_x4(&b_h[jj * 2][0], smem_u32(&sK[0][el]));
                ldm_x4(&b_l[jj * 2][0], smem_u32(&sK[1][el]));
            }
#pragma unroll
            for (int i = 0; i < 2; i++)
#pragma unroll
                for (int j = 0; j < 8; j++) {
                    mma_bf16(acc[i][j], a_h[i], b_h[j]);
                    mma_bf16(acc[i][j], a_h[i], b_l[j]);
                    mma_bf16(acc[i][j], a_l[i], b_h[j]);
                }
        }
        __syncthreads();
    }

    float* Wbh = W + (size_t)bh * S_ * S_;
#pragma unroll
    for (int i = 0; i < 2; i++) {
#pragma unroll
        for (int j = 0; j < 8; j++) {
            int q  = q0 + warp_m + i * 16 + (lane >> 2);
            int k  = k0 + warp_n + j * 8 + (lane & 3) * 2;
            float2 o0, o1;
            o0.x = (k     > q) ? MASKED_BIAS : acc[i][j][0] * 0.125f;
            o0.y = (k + 1 > q) ? MASKED_BIAS : acc[i][j][1] * 0.125f;
            o1.x = (k     > q + 8) ? MASKED_BIAS : acc[i][j][2] * 0.125f;
            o1.y = (k + 1 > q + 8) ? MASKED_BIAS : acc[i][j][3] * 0.125f;
            *reinterpret_cast<float2*>(&Wbh[(size_t)q * S_ + k]) = o0;
            *reinterpret_cast<float2*>(&Wbh[(size_t)(q + 8) * S_ + k]) = o1;
        }
    }
}

// ---------------------------------------------------------------------------
// Softmax in place over each row of W.
// ---------------------------------------------------------------------------
__global__ __launch_bounds__(256)
void softmax_kernel(float* __restrict__ W)
{
    const int tid = threadIdx.x;
    const int row = blockIdx.x;
    const int q = row & (S_ - 1);
    const int nvalid = q + 1;
    float* w = W + (size_t)row * S_;

    __shared__ float red[256];

    float v[8];
    float m = -1e30f;
#pragma unroll
    for (int r = 0; r < 8; r++) {
        int k = tid + r * 256;
        v[r] = (k < nvalid) ? w[k] : -1e30f;
        m = fmaxf(m, v[r]);
    }
    red[tid] = m; __syncthreads();
    for (int off = 128; off > 0; off >>= 1) {
        if (tid < off) red[tid] = fmaxf(red[tid], red[tid + off]);
        __syncthreads();
    }
    const float mx = red[0];
    __syncthreads();

    float s = 0.0f;
#pragma unroll
    for (int r = 0; r < 8; r++) {
        int k = tid + r * 256;
        if (k < nvalid) { v[r] = expf(v[r] - mx); s += v[r]; }
    }
    red[tid] = s; __syncthreads();
    for (int off = 128; off > 0; off >>= 1) {
        if (tid < off) red[tid] += red[tid + off];
        __syncthreads();
    }
    const float inv = 1.0f / red[0];

#pragma unroll
    for (int r = 0; r < 8; r++) {
        int k = tid + r * 256;
        w[k] = (k < nvalid) ? v[r] * inv : 0.0f;
    }
}

// ===========================================================================
// AV on HMMA: g_attn = softmax(W) @ V. A = W (fp32, split in-kernel),
// B = V transposed at smem-store to [d][k]. CTA: 128q x 64d, BK=32 chunks,
// 8 warps, warp tile 16x64. Causal chunk range.
// ===========================================================================
__global__ __launch_bounds__(256)
void av_hmma_kernel(const float* __restrict__ W)
{
    __shared__ __nv_bfloat16 sW[2][128 * SPAD];
    __shared__ __nv_bfloat16 sV[2][64 * SPAD];

    const int tid  = threadIdx.x;
    const int lane = tid & 31;
    const int warp = tid >> 5;
    const int bh   = blockIdx.y;
    const int b    = bh >> 4;
    const int h    = bh & 15;
    const int q0   = blockIdx.x * 128;
    const int warp_m = warp * 16;

    const float* Wbh = W + (size_t)bh * S_ * S_;
    const size_t vbase = (size_t)b * S_ * QKV_N + 2 * D_ + h * DH_;

    float acc[8][4];
#pragma unroll
    for (int j = 0; j < 8; j++)
#pragma unroll
        for (int r = 0; r < 4; r++) acc[j][r] = 0.0f;

    const int a_r = warp_m + (lane & 15);
    const int a_c = (lane >> 4) * 8;
    const int b_r = (lane & 7) + (lane >> 4) * 8;
    const int b_c = ((lane >> 3) & 1) * 8;

    const int wr  = tid >> 1;            // 0..127
    const int wc0 = (tid & 1) * 16;
    const int vd  = tid & 63;            // 0..63
    const int vk0 = (tid >> 6) * 8;      // 0,8,16,24

    const int nch = (blockIdx.x + 1) * 4;
    for (int t = 0; t < nch; t++) {
        const int kc = t * 32;
        // load + split W tile [128 x 32]
#pragma unroll
        for (int i = 0; i < 4; i++) {
            int c = wc0 + i * 4;
            float4 v = *reinterpret_cast<const float4*>(
                &Wbh[(size_t)(q0 + wr) * S_ + kc + c]);
            split4(v, &sW[0][wr * SPAD + c], &sW[1][wr * SPAD + c]);
        }
        // load + split + transpose V tile [32 x 64] -> sV [d][k]
        {
            uint32_t hp[4], lp[4];
#pragma unroll
            for (int i = 0; i < 4; i++) {
                float x0 = g_qkv[vbase + (size_t)(kc + vk0 + 2 * i) * QKV_N + vd];
                float x1 = g_qkv[vbase + (size_t)(kc + vk0 + 2 * i + 1) * QKV_N + vd];
                __nv_bfloat162 hh, ll;
                hh.x = __float2bfloat16(x0); hh.y = __float2bfloat16(x1);
                ll.x = __float2bfloat16(x0 - __bfloat162float(hh.x));
                ll.y = __float2bfloat16(x1 - __bfloat162float(hh.y));
                hp[i] = *reinterpret_cast<uint32_t*>(&hh);
                lp[i] = *reinterpret_cast<uint32_t*>(&ll);
            }
            uint4 hv; hv.x = hp[0]; hv.y = hp[1]; hv.z = hp[2]; hv.w = hp[3];
            uint4 lv; lv.x = lp[0]; lv.y = lp[1]; lv.z = lp[2]; lv.w = lp[3];
            *reinterpret_cast<uint4*>(&sV[0][vd * SPAD + vk0]) = hv;
            *reinterpret_cast<uint4*>(&sV[1][vd * SPAD + vk0]) = lv;
        }
        __syncthreads();

#pragma unroll
        for (int ks = 0; ks < 32; ks += 16) {
            uint32_t a_h[4], a_l[4];
            uint32_t b_h[8][2], b_l[8][2];
            {
                int el = a_r * SPAD + ks + a_c;
                ldm_x4(a_h, smem_u32(&sW[0][el]));
                ldm_x4(a_l, smem_u32(&sW[1][el]));
            }
#pragma unroll
            for (int jj = 0; jj < 4; jj++) {
                int el = (b_r + jj * 16) * SPAD + ks + b_c;
                ldm_x4(&b_h[jj * 2][0], smem_u32(&sV[0][el]));
                ldm_x4(&b_l[jj * 2][0], smem_u32(&sV[1][el]));
            }
#pragma unroll
            for (int j = 0; j < 8; j++) {
                mma_bf16(acc[j], a_h, b_h[j]);
                mma_bf16(acc[j], a_h, b_l[j]);
                mma_bf16(acc[j], a_l, b_h[j]);
            }
        }
        __syncthreads();
    }

    // epilogue: write g_attn rows
#pragma unroll
    for (int j = 0; j < 8; j++) {
        int m = q0 + warp_m + (lane >> 2);
        int n = j * 8 + (lane & 3) * 2;
        float2 o0; o0.x = acc[j][0]; o0.y = acc[j][1];
        float2 o1; o1.x = acc[j][2]; o1.y = acc[j][3];
        *reinterpret_cast<float2*>(
            &g_attn[(size_t)(b * S_ + m) * D_ + h * DH_ + n]) = o0;
        *reinterpret_cast<float2*>(
            &g_attn[(size_t)(b * S_ + m + 8) * D_ + h * DH_ + n]) = o1;
    }
}

// ---------------------------------------------------------------------------
extern "C" void kernel_launch(void* const* d_in, const int* in_sizes, int n_in,
                              void* d_out, int out_size)
{
    const float* hs       = (const float*)d_in[0];  // [2,2048,1024]
    const float* c_attn_w = (const float*)d_in[1];  // [1024,3072]
    const float* c_attn_b = (const float*)d_in[2];  // [3072]
    const float* c_proj_w = (const float*)d_in[3];  // [1024,1024]
    const float* c_proj_b = (const float*)d_in[4];  // [1024]

    float* out  = (float*)d_out;
    float* Wout = out + OUT_ATTN_ELEMS;

    float *qkv_ptr = nullptr, *attn_ptr = nullptr;
    __nv_bfloat16 *ahi, *alo, *w1hi, *w1lo, *w2hi, *w2lo;
    cudaGetSymbolAddress((void**)&qkv_ptr, g_qkv);
    cudaGetSymbolAddress((void**)&attn_ptr, g_attn);
    cudaGetSymbolAddress((void**)&ahi,  g_ahi);
    cudaGetSymbolAddress((void**)&alo,  g_alo);
    cudaGetSymbolAddress((void**)&w1hi, g_w1hi);
    cudaGetSymbolAddress((void**)&w1lo, g_w1lo);
    cudaGetSymbolAddress((void**)&w2hi, g_w2hi);
    cudaGetSymbolAddress((void**)&w2lo, g_w2lo);

    // 0) splits for dense GEMMs
    split_rows_kernel<<<(BS_ * D_ / 4 + 255) / 256, 256>>>(hs, ahi, alo, BS_ * D_ / 4);
    split_T_kernel<<<dim3(QKV_N / 32, D_ / 32), 256>>>(c_attn_w, w1hi, w1lo, D_, QKV_N);
    split_T_kernel<<<dim3(D_ / 32, D_ / 32), 256>>>(c_proj_w, w2hi, w2lo, D_, D_);

    // 1) QKV GEMM (HMMA)
    gemm_hmma_kernel<<<dim3(QKV_N / 128, BS_ / 128), 256>>>(
        ahi, alo, w1hi, w1lo, c_attn_b, qkv_ptr, BS_, QKV_N, D_);

    // 2) Scores (HMMA, lower-triangle tiles only)
    scores_hmma_kernel<<<dim3(136, B_ * H_), 256>>>(Wout);

    // 3) Softmax in place
    softmax_kernel<<<B_ * H_ * S_, 256>>>(Wout);

    // 4) AV (HMMA) -> g_attn
    av_hmma_kernel<<<dim3(S_ / 128, B_ * H_), 256>>>(Wout);

    // 5) split attn output, then proj GEMM (HMMA)
    split_rows_kernel<<<(BS_ * D_ / 4 + 255) / 256, 256>>>(attn_ptr, ahi, alo, BS_ * D_ / 4);
    gemm_hmma_kernel<<<dim3(D_ / 128, BS_ / 128), 256>>>(
        ahi, alo, w2hi, w2lo, c_proj_b, out, BS_, D_, D_);
}

// round 5
// speedup vs baseline: 1.8731x; 1.0024x over previous
#include <cuda_runtime.h>
#include <cuda_bf16.h>
#include <cstdint>
#include <cstddef>

// Problem constants
#define B_   2
#define S_   2048
#define D_   1024
#define H_   16
#define DH_  64
#define BS_  (B_ * S_)            // 4096
#define QKV_N (3 * D_)            // 3072
#define OUT_ATTN_ELEMS ((size_t)BS_ * D_)           // 4,194,304
#define MASKED_BIAS -10000.0f

// Scratch (allocation-free rule: __device__ globals)
__device__ float g_qkv[BS_ * QKV_N];   // [4096, 3072] : Q | K | V packed (fp32)
__device__ float g_attn[BS_ * D_];     // [4096, 1024] : pre-proj attn output
// bf16 split operands for the dense GEMMs
__device__ __nv_bfloat16 g_ahi[BS_ * D_];
__device__ __nv_bfloat16 g_alo[BS_ * D_];
__device__ __nv_bfloat16 g_w1hi[QKV_N * D_];   // c_attn_w^T [3072,1024]
__device__ __nv_bfloat16 g_w1lo[QKV_N * D_];
__device__ __nv_bfloat16 g_w2hi[D_ * D_];      // c_proj_w^T [1024,1024]
__device__ __nv_bfloat16 g_w2lo[D_ * D_];

// ===========================================================================
// HMMA / async-copy helpers
// ===========================================================================
__device__ __forceinline__ uint32_t smem_u32(const void* p) {
    uint32_t a;
    asm("{ .reg .u64 t; cvta.to.shared.u64 t, %1; cvt.u32.u64 %0, t; }"
        : "=r"(a) : "l"(p));
    return a;
}

__device__ __forceinline__ void ldm_x4(uint32_t r[4], uint32_t saddr) {
    asm volatile("ldmatrix.sync.aligned.m8n8.x4.shared.b16 {%0,%1,%2,%3}, [%4];"
                 : "=r"(r[0]), "=r"(r[1]), "=r"(r[2]), "=r"(r[3]) : "r"(saddr));
}

__device__ __forceinline__ void mma_bf16(float c[4], const uint32_t a[4],
                                         const uint32_t b[2]) {
    asm volatile(
        "mma.sync.aligned.m16n8k16.row.col.f32.bf16.bf16.f32 "
        "{%0,%1,%2,%3}, {%4,%5,%6,%7}, {%8,%9}, {%0,%1,%2,%3};"
        : "+f"(c[0]), "+f"(c[1]), "+f"(c[2]), "+f"(c[3])
        : "r"(a[0]), "r"(a[1]), "r"(a[2]), "r"(a[3]), "r"(b[0]), "r"(b[1]));
}

__device__ __forceinline__ void cp16(uint32_t saddr, const void* gaddr) {
    asm volatile("cp.async.ca.shared.global [%0], [%1], 16;"
                 :: "r"(saddr), "l"(gaddr));
}
#define CP_COMMIT() asm volatile("cp.async.commit_group;" ::: "memory")
#define CP_WAIT(N)  asm volatile("cp.async.wait_group %0;" :: "n"(N) : "memory")

// Split a float4 into hi/lo bf16x4, store as 8B each.
__device__ __forceinline__ void split4(float4 v, __nv_bfloat16* hp,
                                       __nv_bfloat16* lp)
{
    __nv_bfloat162 h0, h1, l0, l1;
    h0.x = __float2bfloat16(v.x); h0.y = __float2bfloat16(v.y);
    h1.x = __float2bfloat16(v.z); h1.y = __float2bfloat16(v.w);
    l0.x = __float2bfloat16(v.x - __bfloat162float(h0.x));
    l0.y = __float2bfloat16(v.y - __bfloat162float(h0.y));
    l1.x = __float2bfloat16(v.z - __bfloat162float(h1.x));
    l1.y = __float2bfloat16(v.w - __bfloat162float(h1.y));
    uint2 hu, lu;
    hu.x = *reinterpret_cast<uint32_t*>(&h0);
    hu.y = *reinterpret_cast<uint32_t*>(&h1);
    lu.x = *reinterpret_cast<uint32_t*>(&l0);
    lu.y = *reinterpret_cast<uint32_t*>(&l1);
    *reinterpret_cast<uint2*>(hp) = hu;
    *reinterpret_cast<uint2*>(lp) = lu;
}

// ===========================================================================
// Split kernels: fp32 -> bf16 hi/lo (for dense GEMM operands)
// ===========================================================================
__global__ __launch_bounds__(256)
void split_rows_kernel(const float* __restrict__ in,
                       __nv_bfloat16* __restrict__ hi,
                       __nv_bfloat16* __restrict__ lo, int n4)
{
    int i = blockIdx.x * 256 + threadIdx.x;
    if (i >= n4) return;
    float4 v = reinterpret_cast<const float4*>(in)[i];
    split4(v, hi + i * 4, lo + i * 4);
}

// Transpose + split: in [K,N] fp32 -> out [N,K] bf16 hi/lo
__global__ __launch_bounds__(256)
void split_T_kernel(const float* __restrict__ in,
                    __nv_bfloat16* __restrict__ hi,
                    __nv_bfloat16* __restrict__ lo, int K, int N)
{
    __shared__ float t[32][33];
    int n0 = blockIdx.x * 32, k0 = blockIdx.y * 32;
    int tx = threadIdx.x & 31, ty = threadIdx.x >> 5;   // 32 x 8
#pragma unroll
    for (int i = 0; i < 4; i++)
        t[ty + 8 * i][tx] = in[(size_t)(k0 + ty + 8 * i) * N + n0 + tx];
    __syncthreads();
#pragma unroll
    for (int i = 0; i < 4; i++) {
        float v = t[tx][ty + 8 * i];
        __nv_bfloat16 h = __float2bfloat16(v);
        __nv_bfloat16 l = __float2bfloat16(v - __bfloat162float(h));
        size_t o = (size_t)(n0 + ty + 8 * i) * K + k0 + tx;
        hi[o] = h;
        lo[o] = l;
    }
}

// ===========================================================================
// cp.async double-buffered HMMA GEMM:
// C[M,N] = (Ahi+Alo)[M,K] @ (Bhi+Blo)[N,K]^T + bias[N]
// 128x128 CTA tile, BK=32, 8 warps (4m x 2n), warp tile 32x64.
// ===========================================================================
#define SPAD    40
#define TILE_E  (128 * SPAD)          // elements per tile
#define STAGE_E (4 * TILE_E)          // Ahi, Alo, Bhi, Blo
#define GEMM_SMEM_BYTES (2 * STAGE_E * 2)   // 2 stages * bf16

__device__ __forceinline__ void gemm_issue_loads(
    const __nv_bfloat16* __restrict__ Ahi, const __nv_bfloat16* __restrict__ Alo,
    const __nv_bfloat16* __restrict__ Bhi, const __nv_bfloat16* __restrict__ Blo,
    uint32_t sm_base, int stage, int row0, int col0, int kk, int K, int tid)
{
    const uint32_t st = sm_base + (uint32_t)stage * STAGE_E * 2;
#pragma unroll
    for (int u = 0; u < 2; u++) {
        int s  = tid + u * 256;
        int r  = s >> 2;
        int cg = (s & 3) * 8;
        size_t goffA = (size_t)(row0 + r) * K + kk + cg;
        size_t goffB = (size_t)(col0 + r) * K + kk + cg;
        uint32_t so = (uint32_t)(r * SPAD + cg) * 2;
        cp16(st + 0 * TILE_E * 2 + so, Ahi + goffA);
        cp16(st + 1 * TILE_E * 2 + so, Alo + goffA);
        cp16(st + 2 * TILE_E * 2 + so, Bhi + goffB);
        cp16(st + 3 * TILE_E * 2 + so, Blo + goffB);
    }
}

__global__ __launch_bounds__(256)
void gemm_hmma_async(const __nv_bfloat16* __restrict__ Ahi,
                     const __nv_bfloat16* __restrict__ Alo,
                     const __nv_bfloat16* __restrict__ Bhi,
                     const __nv_bfloat16* __restrict__ Blo,
                     const float* __restrict__ bias,
                     float* __restrict__ C, int M, int N, int K)
{
    extern __shared__ __nv_bfloat16 sm[];
    const uint32_t sm_base = smem_u32(sm);

    const int tid  = threadIdx.x;
    const int lane = tid & 31;
    const int warp = tid >> 5;
    const int row0 = blockIdx.y * 128;
    const int col0 = blockIdx.x * 128;
    const int warp_m = (warp & 3) * 32;
    const int warp_n = (warp >> 2) * 64;

    float acc[2][8][4];
#pragma unroll
    for (int i = 0; i < 2; i++)
#pragma unroll
        for (int j = 0; j < 8; j++)
#pragma unroll
            for (int r = 0; r < 4; r++) acc[i][j][r] = 0.0f;

    const int a_r = warp_m + (lane & 15);
    const int a_c = (lane >> 4) * 8;
    const int b_r = warp_n + (lane & 7) + (lane >> 4) * 8;
    const int b_c = ((lane >> 3) & 1) * 8;

    const int nch = K >> 5;   // K / 32

    // prologue: chunk 0 -> stage 0
    gemm_issue_loads(Ahi, Alo, Bhi, Blo, sm_base, 0, row0, col0, 0, K, tid);
    CP_COMMIT();

    for (int c = 0; c < nch; c++) {
        const int cur = c & 1;
        if (c + 1 < nch) {
            gemm_issue_loads(Ahi, Alo, Bhi, Blo, sm_base, cur ^ 1,
                             row0, col0, (c + 1) << 5, K, tid);
            CP_COMMIT();
            CP_WAIT(1);
        } else {
            CP_WAIT(0);
        }
        __syncthreads();

        const __nv_bfloat16* sAhi = sm + cur * STAGE_E + 0 * TILE_E;
        const __nv_bfloat16* sAlo = sm + cur * STAGE_E + 1 * TILE_E;
        const __nv_bfloat16* sBhi = sm + cur * STAGE_E + 2 * TILE_E;
        const __nv_bfloat16* sBlo = sm + cur * STAGE_E + 3 * TILE_E;

#pragma unroll
        for (int ks = 0; ks < 32; ks += 16) {
            uint32_t a_h[2][4], a_l[2][4];
            uint32_t b_h[8][2], b_l[8][2];
#pragma unroll
            for (int i = 0; i < 2; i++) {
                int el = (a_r + i * 16) * SPAD + ks + a_c;
                ldm_x4(a_h[i], smem_u32(sAhi + el));
                ldm_x4(a_l[i], smem_u32(sAlo + el));
            }
#pragma unroll
            for (int jj = 0; jj < 4; jj++) {
                int el = (b_r + jj * 16) * SPAD + ks + b_c;
                ldm_x4(&b_h[jj * 2][0], smem_u32(sBhi + el));
                ldm_x4(&b_l[jj * 2][0], smem_u32(sBlo + el));
            }
#pragma unroll
            for (int i = 0; i < 2; i++)
#pragma unroll
                for (int j = 0; j < 8; j++) {
                    mma_bf16(acc[i][j], a_h[i], b_h[j]);
                    mma_bf16(acc[i][j], a_h[i], b_l[j]);
                    mma_bf16(acc[i][j], a_l[i], b_h[j]);
                }
        }
        __syncthreads();
    }

#pragma unroll
    for (int i = 0; i < 2; i++) {
#pragma unroll
        for (int j = 0; j < 8; j++) {
            int m = row0 + warp_m + i * 16 + (lane >> 2);
            int n = col0 + warp_n + j * 8 + (lane & 3) * 2;
            float2 bz = *reinterpret_cast<const float2*>(&bias[n]);
            float2 o0; o0.x = acc[i][j][0] + bz.x; o0.y = acc[i][j][1] + bz.y;
            float2 o1; o1.x = acc[i][j][2] + bz.x; o1.y = acc[i][j][3] + bz.y;
            *reinterpret_cast<float2*>(&C[(size_t)m * N + n]) = o0;
            *reinterpret_cast<float2*>(&C[(size_t)(m + 8) * N + n]) = o1;
        }
    }
}

// ===========================================================================
// Scores on HMMA: W[bh,q,k] = (Q.K)/8, masked. Lower-triangle tiles only.
// ===========================================================================
__global__ __launch_bounds__(256)
void scores_hmma_kernel(float* __restrict__ W)
{
    __shared__ __nv_bfloat16 sQ[2][128 * SPAD];
    __shared__ __nv_bfloat16 sK[2][128 * SPAD];

    const int tid  = threadIdx.x;
    const int lane = tid & 31;
    const int warp = tid >> 5;
    const int bh   = blockIdx.y;
    const int b    = bh >> 4;
    const int h    = bh & 15;

    int pair = blockIdx.x;
    int qt = (int)((-1.0f + sqrtf(1.0f + 8.0f * (float)pair)) * 0.5f);
    while ((qt + 1) * (qt + 2) / 2 <= pair) ++qt;
    while (qt * (qt + 1) / 2 > pair) --qt;
    const int kt = pair - qt * (qt + 1) / 2;

    const int q0 = qt * 128;
    const int k0 = kt * 128;
    const int warp_m = (warp & 3) * 32;
    const int warp_n = (warp >> 2) * 64;

    float acc[2][8][4];
#pragma unroll
    for (int i = 0; i < 2; i++)
#pragma unroll
        for (int j = 0; j < 8; j++)
#pragma unroll
            for (int r = 0; r < 4; r++) acc[i][j][r] = 0.0f;

    const int a_r = warp_m + (lane & 15);
    const int a_c = (lane >> 4) * 8;
    const int b_r = warp_n + (lane & 7) + (lane >> 4) * 8;
    const int b_c = ((lane >> 3) & 1) * 8;

    const size_t qbase = (size_t)(b * S_ + q0) * QKV_N + h * DH_;
    const size_t kbase = (size_t)(b * S_ + k0) * QKV_N + D_ + h * DH_;

    const int lr = tid >> 1;
    const int lc0 = (tid & 1) * 16;

    for (int dc = 0; dc < DH_; dc += 32) {
#pragma unroll
        for (int i = 0; i < 4; i++) {
            int c = lc0 + i * 4;
            float4 vq = *reinterpret_cast<const float4*>(
                &g_qkv[qbase + (size_t)lr * QKV_N + dc + c]);
            float4 vk = *reinterpret_cast<const float4*>(
                &g_qkv[kbase + (size_t)lr * QKV_N + dc + c]);
            split4(vq, &sQ[0][lr * SPAD + c], &sQ[1][lr * SPAD + c]);
            split4(vk, &sK[0][lr * SPAD + c], &sK[1][lr * SPAD + c]);
        }
        __syncthreads();

#pragma unroll
        for (int ks = 0; ks < 32; ks += 16) {
            uint32_t a_h[2][4], a_l[2][4];
            uint32_t b_h[8][2], b_l[8][2];
#pragma unroll
            for (int i = 0; i < 2; i++) {
                int el = (a_r + i * 16) * SPAD + ks + a_c;
                ldm_x4(a_h[i], smem_u32(&sQ[0][el]));
                ldm_x4(a_l[i], smem_u32(&sQ[1][el]));
            }
#pragma unroll
            for (int jj = 0; jj < 4; jj++) {
                int el = (b_r + jj * 16) * SPAD + ks + b_c;
                ldm_x4(&b_h[jj * 2][0], smem_u32(&sK[0][el]));
                ldm_x4(&b_l[jj * 2][0], smem_u32(&sK[1][el]));
            }
#pragma unroll
            for (int i = 0; i < 2; i++)
#pragma unroll
                for (int j = 0; j < 8; j++) {
                    mma_bf16(acc[i][j], a_h[i], b_h[j]);
                    mma_bf16(acc[i][j], a_h[i], b_l[j]);
                    mma_bf16(acc[i][j], a_l[i], b_h[j]);
                }
        }
        __syncthreads();
    }

    float* Wbh = W + (size_t)bh * S_ * S_;
#pragma unroll
    for (int i = 0; i < 2; i++) {
#pragma unroll
        for (int j = 0; j < 8; j++) {
            int q  = q0 + warp_m + i * 16 + (lane >> 2);
            int k  = k0 + warp_n + j * 8 + (lane & 3) * 2;
            float2 o0, o1;
            o0.x = (k     > q) ? MASKED_BIAS : acc[i][j][0] * 0.125f;
            o0.y = (k + 1 > q) ? MASKED_BIAS : acc[i][j][1] * 0.125f;
            o1.x = (k     > q + 8) ? MASKED_BIAS : acc[i][j][2] * 0.125f;
            o1.y = (k + 1 > q + 8) ? MASKED_BIAS : acc[i][j][3] * 0.125f;
            *reinterpret_cast<float2*>(&Wbh[(size_t)q * S_ + k]) = o0;
            *reinterpret_cast<float2*>(&Wbh[(size_t)(q + 8) * S_ + k]) = o1;
        }
    }
}

// ---------------------------------------------------------------------------
// Softmax in place: float4 IO, warp-shuffle reductions, __expf.
// One block (256 thr) per row; 2 float4 per thread.
// ---------------------------------------------------------------------------
__global__ __launch_bounds__(256)
void softmax_kernel(float* __restrict__ W)
{
    const int tid = threadIdx.x;
    const int lane = tid & 31;
    const int warp = tid >> 5;
    const int row = blockIdx.x;
    const int q = row & (S_ - 1);
    const int nvalid = q + 1;
    float* w = W + (size_t)row * S_;

    __shared__ float red[8];

    float4 v[2];
    float m = -1e30f;
#pragma unroll
    for (int r = 0; r < 2; r++) {
        int k0 = (r * 256 + tid) * 4;
        float4 x = *reinterpret_cast<const float4*>(w + k0);
        x.x = (k0 + 0 < nvalid) ? x.x : -1e30f;
        x.y = (k0 + 1 < nvalid) ? x.y : -1e30f;
        x.z = (k0 + 2 < nvalid) ? x.z : -1e30f;
        x.w = (k0 + 3 < nvalid) ? x.w : -1e30f;
        v[r] = x;
        m = fmaxf(m, fmaxf(fmaxf(x.x, x.y), fmaxf(x.z, x.w)));
    }
#pragma unroll
    for (int off = 16; off > 0; off >>= 1)
        m = fmaxf(m, __shfl_xor_sync(0xFFFFFFFFu, m, off));
    if (lane == 0) red[warp] = m;
    __syncthreads();
    float mx = red[0];
#pragma unroll
    for (int i = 1; i < 8; i++) mx = fmaxf(mx, red[i]);
    __syncthreads();

    float s = 0.0f;
#pragma unroll
    for (int r = 0; r < 2; r++) {
        int k0 = (r * 256 + tid) * 4;
        float4 x = v[r];
        x.x = (k0 + 0 < nvalid) ? __expf(x.x - mx) : 0.0f;
        x.y = (k0 + 1 < nvalid) ? __expf(x.y - mx) : 0.0f;
        x.z = (k0 + 2 < nvalid) ? __expf(x.z - mx) : 0.0f;
        x.w = (k0 + 3 < nvalid) ? __expf(x.w - mx) : 0.0f;
        v[r] = x;
        s += x.x + x.y + x.z + x.w;
    }
#pragma unroll
    for (int off = 16; off > 0; off >>= 1)
        s += __shfl_xor_sync(0xFFFFFFFFu, s, off);
    if (lane == 0) red[warp] = s;
    __syncthreads();
    float tot = red[0];
#pragma unroll
    for (int i = 1; i < 8; i++) tot += red[i];
    const float inv = 1.0f / tot;

#pragma unroll
    for (int r = 0; r < 2; r++) {
        int k0 = (r * 256 + tid) * 4;
        float4 x = v[r];
        x.x *= inv; x.y *= inv; x.z *= inv; x.w *= inv;
        *reinterpret_cast<float4*>(w + k0) = x;
    }
}

// ===========================================================================
// AV on HMMA: g_attn = softmax(W) @ V. Causal chunk range.
// ===========================================================================
__global__ __launch_bounds__(256)
void av_hmma_kernel(const float* __restrict__ W)
{
    __shared__ __nv_bfloat16 sW[2][128 * SPAD];
    __shared__ __nv_bfloat16 sV[2][64 * SPAD];

    const int tid  = threadIdx.x;
    const int lane = tid & 31;
    const int warp = tid >> 5;
    const int bh   = blockIdx.y;
    const int b    = bh >> 4;
    const int h    = bh & 15;
    const int q0   = blockIdx.x * 128;
    const int warp_m = warp * 16;

    const float* Wbh = W + (size_t)bh * S_ * S_;
    const size_t vbase = (size_t)b * S_ * QKV_N + 2 * D_ + h * DH_;

    float acc[8][4];
#pragma unroll
    for (int j = 0; j < 8; j++)
#pragma unroll
        for (int r = 0; r < 4; r++) acc[j][r] = 0.0f;

    const int a_r = warp_m + (lane & 15);
    const int a_c = (lane >> 4) * 8;
    const int b_r = (lane & 7) + (lane >> 4) * 8;
    const int b_c = ((lane >> 3) & 1) * 8;

    const int wr  = tid >> 1;
    const int wc0 = (tid & 1) * 16;
    const int vd  = tid & 63;
    const int vk0 = (tid >> 6) * 8;

    const int nch = (blockIdx.x + 1) * 4;
    for (int t = 0; t < nch; t++) {
        const int kc = t * 32;
#pragma unroll
        for (int i = 0; i < 4; i++) {
            int c = wc0 + i * 4;
            float4 v = *reinterpret_cast<const float4*>(
                &Wbh[(size_t)(q0 + wr) * S_ + kc + c]);
            split4(v, &sW[0][wr * SPAD + c], &sW[1][wr * SPAD + c]);
        }
        {
            uint32_t hp[4], lp[4];
#pragma unroll
            for (int i = 0; i < 4; i++) {
                float x0 = g_qkv[vbase + (size_t)(kc + vk0 + 2 * i) * QKV_N + vd];
                float x1 = g_qkv[vbase + (size_t)(kc + vk0 + 2 * i + 1) * QKV_N + vd];
                __nv_bfloat162 hh, ll;
                hh.x = __float2bfloat16(x0); hh.y = __float2bfloat16(x1);
                ll.x = __float2bfloat16(x0 - __bfloat162float(hh.x));
                ll.y = __float2bfloat16(x1 - __bfloat162float(hh.y));
                hp[i] = *reinterpret_cast<uint32_t*>(&hh);
                lp[i] = *reinterpret_cast<uint32_t*>(&ll);
            }
            uint4 hv; hv.x = hp[0]; hv.y = hp[1]; hv.z = hp[2]; hv.w = hp[3];
            uint4 lv; lv.x = lp[0]; lv.y = lp[1]; lv.z = lp[2]; lv.w = lp[3];
            *reinterpret_cast<uint4*>(&sV[0][vd * SPAD + vk0]) = hv;
            *reinterpret_cast<uint4*>(&sV[1][vd * SPAD + vk0]) = lv;
        }
        __syncthreads();

#pragma unroll
        for (int ks = 0; ks < 32; ks += 16) {
            uint32_t a_h[4], a_l[4];
            uint32_t b_h[8][2], b_l[8][2];
            {
                int el = a_r * SPAD + ks + a_c;
                ldm_x4(a_h, smem_u32(&sW[0][el]));
                ldm_x4(a_l, smem_u32(&sW[1][el]));
            }
#pragma unroll
            for (int jj = 0; jj < 4; jj++) {
                int el = (b_r + jj * 16) * SPAD + ks + b_c;
                ldm_x4(&b_h[jj * 2][0], smem_u32(&sV[0][el]));
                ldm_x4(&b_l[jj * 2][0], smem_u32(&sV[1][el]));
            }
#pragma unroll
            for (int j = 0; j < 8; j++) {
                mma_bf16(acc[j], a_h, b_h[j]);
                mma_bf16(acc[j], a_h, b_l[j]);
                mma_bf16(acc[j], a_l, b_h[j]);
            }
        }
        __syncthreads();
    }

#pragma unroll
    for (int j = 0; j < 8; j++) {
        int m = q0 + warp_m + (lane >> 2);
        int n = j * 8 + (lane & 3) * 2;
        float2 o0; o0.x = acc[j][0]; o0.y = acc[j][1];
        float2 o1; o1.x = acc[j][2]; o1.y = acc[j][3];
        *reinterpret_cast<float2*>(
            &g_attn[(size_t)(b * S_ + m) * D_ + h * DH_ + n]) = o0;
        *reinterpret_cast<float2*>(
            &g_attn[(size_t)(b * S_ + m + 8) * D_ + h * DH_ + n]) = o1;
    }
}

// ---------------------------------------------------------------------------
extern "C" void kernel_launch(void* const* d_in, const int* in_sizes, int n_in,
                              void* d_out, int out_size)
{
    const float* hs       = (const float*)d_in[0];  // [2,2048,1024]
    const float* c_attn_w = (const float*)d_in[1];  // [1024,3072]
    const float* c_attn_b = (const float*)d_in[2];  // [3072]
    const float* c_proj_w = (const float*)d_in[3];  // [1024,1024]
    const float* c_proj_b = (const float*)d_in[4];  // [1024]

    float* out  = (float*)d_out;
    float* Wout = out + OUT_ATTN_ELEMS;

    float *qkv_ptr = nullptr, *attn_ptr = nullptr;
    __nv_bfloat16 *ahi, *alo, *w1hi, *w1lo, *w2hi, *w2lo;
    cudaGetSymbolAddress((void**)&qkv_ptr, g_qkv);
    cudaGetSymbolAddress((void**)&attn_ptr, g_attn);
    cudaGetSymbolAddress((void**)&ahi,  g_ahi);
    cudaGetSymbolAddress((void**)&alo,  g_alo);
    cudaGetSymbolAddress((void**)&w1hi, g_w1hi);
    cudaGetSymbolAddress((void**)&w1lo, g_w1lo);
    cudaGetSymbolAddress((void**)&w2hi, g_w2hi);
    cudaGetSymbolAddress((void**)&w2lo, g_w2lo);

    static bool attr_set = false;
    if (!attr_set) {
        cudaFuncSetAttribute(gemm_hmma_async,
                             cudaFuncAttributeMaxDynamicSharedMemorySize,
                             GEMM_SMEM_BYTES);
        attr_set = true;
    }

    // 0) splits for dense GEMMs
    split_rows_kernel<<<(BS_ * D_ / 4 + 255) / 256, 256>>>(hs, ahi, alo, BS_ * D_ / 4);
    split_T_kernel<<<dim3(QKV_N / 32, D_ / 32), 256>>>(c_attn_w, w1hi, w1lo, D_, QKV_N);
    split_T_kernel<<<dim3(D_ / 32, D_ / 32), 256>>>(c_proj_w, w2hi, w2lo, D_, D_);

    // 1) QKV GEMM (HMMA, cp.async pipelined)
    gemm_hmma_async<<<dim3(QKV_N / 128, BS_ / 128), 256, GEMM_SMEM_BYTES>>>(
        ahi, alo, w1hi, w1lo, c_attn_b, qkv_ptr, BS_, QKV_N, D_);

    // 2) Scores (HMMA, lower-triangle tiles only)
    scores_hmma_kernel<<<dim3(136, B_ * H_), 256>>>(Wout);

    // 3) Softmax in place
    softmax_kernel<<<B_ * H_ * S_, 256>>>(Wout);

    // 4) AV (HMMA) -> g_attn
    av_hmma_kernel<<<dim3(S_ / 128, B_ * H_), 256>>>(Wout);

    // 5) split attn output, then proj GEMM (HMMA, pipelined)
    split_rows_kernel<<<(BS_ * D_ / 4 + 255) / 256, 256>>>(attn_ptr, ahi, alo, BS_ * D_ / 4);
    gemm_hmma_async<<<dim3(D_ / 128, BS_ / 128), 256, GEMM_SMEM_BYTES>>>(
        ahi, alo, w2hi, w2lo, c_proj_b, out, BS_, D_, D_);
}

// round 6
// speedup vs baseline: 2.0242x; 1.0807x over previous
#include <cuda_runtime.h>
#include <cuda_bf16.h>
#include <cstdint>
#include <cstddef>

// Problem constants
#define B_   2
#define S_   2048
#define D_   1024
#define H_   16
#define DH_  64
#define BS_  (B_ * S_)            // 4096
#define QKV_N (3 * D_)            // 3072
#define OUT_ATTN_ELEMS ((size_t)BS_ * D_)           // 4,194,304
#define MASKED_BIAS -10000.0f

// Scratch (allocation-free rule: __device__ globals)
__device__ float g_qkv[BS_ * QKV_N];   // [4096, 3072] : Q | K | V packed (fp32)
__device__ float g_attn[BS_ * D_];     // [4096, 1024] : pre-proj attn output
// bf16 split operands for the dense GEMMs
__device__ __nv_bfloat16 g_ahi[BS_ * D_];
__device__ __nv_bfloat16 g_alo[BS_ * D_];
__device__ __nv_bfloat16 g_w1hi[QKV_N * D_];   // c_attn_w^T [3072,1024]
__device__ __nv_bfloat16 g_w1lo[QKV_N * D_];
__device__ __nv_bfloat16 g_w2hi[D_ * D_];      // c_proj_w^T [1024,1024]
__device__ __nv_bfloat16 g_w2lo[D_ * D_];

// ===========================================================================
// HMMA / async-copy helpers
// ===========================================================================
__device__ __forceinline__ uint32_t smem_u32(const void* p) {
    uint32_t a;
    asm("{ .reg .u64 t; cvta.to.shared.u64 t, %1; cvt.u32.u64 %0, t; }"
        : "=r"(a) : "l"(p));
    return a;
}

__device__ __forceinline__ void ldm_x4(uint32_t r[4], uint32_t saddr) {
    asm volatile("ldmatrix.sync.aligned.m8n8.x4.shared.b16 {%0,%1,%2,%3}, [%4];"
                 : "=r"(r[0]), "=r"(r[1]), "=r"(r[2]), "=r"(r[3]) : "r"(saddr));
}

__device__ __forceinline__ void mma_bf16(float c[4], const uint32_t a[4],
                                         const uint32_t b[2]) {
    asm volatile(
        "mma.sync.aligned.m16n8k16.row.col.f32.bf16.bf16.f32 "
        "{%0,%1,%2,%3}, {%4,%5,%6,%7}, {%8,%9}, {%0,%1,%2,%3};"
        : "+f"(c[0]), "+f"(c[1]), "+f"(c[2]), "+f"(c[3])
        : "r"(a[0]), "r"(a[1]), "r"(a[2]), "r"(a[3]), "r"(b[0]), "r"(b[1]));
}

__device__ __forceinline__ void cp16(uint32_t saddr, const void* gaddr) {
    asm volatile("cp.async.ca.shared.global [%0], [%1], 16;"
                 :: "r"(saddr), "l"(gaddr));
}
#define CP_COMMIT() asm volatile("cp.async.commit_group;" ::: "memory")
#define CP_WAIT(N)  asm volatile("cp.async.wait_group %0;" :: "n"(N) : "memory")

// Split a float4 into hi/lo bf16x4, store as 8B each.
__device__ __forceinline__ void split4(float4 v, __nv_bfloat16* hp,
                                       __nv_bfloat16* lp)
{
    __nv_bfloat162 h0, h1, l0, l1;
    h0.x = __float2bfloat16(v.x); h0.y = __float2bfloat16(v.y);
    h1.x = __float2bfloat16(v.z); h1.y = __float2bfloat16(v.w);
    l0.x = __float2bfloat16(v.x - __bfloat162float(h0.x));
    l0.y = __float2bfloat16(v.y - __bfloat162float(h0.y));
    l1.x = __float2bfloat16(v.z - __bfloat162float(h1.x));
    l1.y = __float2bfloat16(v.w - __bfloat162float(h1.y));
    uint2 hu, lu;
    hu.x = *reinterpret_cast<uint32_t*>(&h0);
    hu.y = *reinterpret_cast<uint32_t*>(&h1);
    lu.x = *reinterpret_cast<uint32_t*>(&l0);
    lu.y = *reinterpret_cast<uint32_t*>(&l1);
    *reinterpret_cast<uint2*>(hp) = hu;
    *reinterpret_cast<uint2*>(lp) = lu;
}

// ===========================================================================
// Split kernels: fp32 -> bf16 hi/lo (for dense GEMM operands)
// ===========================================================================
__global__ __launch_bounds__(256)
void split_rows_kernel(const float* __restrict__ in,
                       __nv_bfloat16* __restrict__ hi,
                       __nv_bfloat16* __restrict__ lo, int n4)
{
    int i = blockIdx.x * 256 + threadIdx.x;
    if (i >= n4) return;
    float4 v = reinterpret_cast<const float4*>(in)[i];
    split4(v, hi + i * 4, lo + i * 4);
}

// Transpose + split: in [K,N] fp32 -> out [N,K] bf16 hi/lo
__global__ __launch_bounds__(256)
void split_T_kernel(const float* __restrict__ in,
                    __nv_bfloat16* __restrict__ hi,
                    __nv_bfloat16* __restrict__ lo, int K, int N)
{
    __shared__ float t[32][33];
    int n0 = blockIdx.x * 32, k0 = blockIdx.y * 32;
    int tx = threadIdx.x & 31, ty = threadIdx.x >> 5;   // 32 x 8
#pragma unroll
    for (int i = 0; i < 4; i++)
        t[ty + 8 * i][tx] = in[(size_t)(k0 + ty + 8 * i) * N + n0 + tx];
    __syncthreads();
#pragma unroll
    for (int i = 0; i < 4; i++) {
        float v = t[tx][ty + 8 * i];
        __nv_bfloat16 h = __float2bfloat16(v);
        __nv_bfloat16 l = __float2bfloat16(v - __bfloat162float(h));
        size_t o = (size_t)(n0 + ty + 8 * i) * K + k0 + tx;
        hi[o] = h;
        lo[o] = l;
    }
}

// ===========================================================================
// cp.async double-buffered HMMA GEMM:
// C[M,N] = (Ahi+Alo)[M,K] @ (Bhi+Blo)[N,K]^T + bias[N]
// 128x128 CTA tile, BK=32, 8 warps (4m x 2n), warp tile 32x64.
// MMA issue is PASS-MAJOR: all hi*hi, then hi*lo, then lo*hi — each
// accumulator re-touched only every 16 MMAs (no dependency chains).
// ===========================================================================
#define SPAD    40
#define TILE_E  (128 * SPAD)          // elements per tile
#define STAGE_E (4 * TILE_E)          // Ahi, Alo, Bhi, Blo
#define GEMM_SMEM_BYTES (2 * STAGE_E * 2)   // 2 stages * bf16

__device__ __forceinline__ void gemm_issue_loads(
    const __nv_bfloat16* __restrict__ Ahi, const __nv_bfloat16* __restrict__ Alo,
    const __nv_bfloat16* __restrict__ Bhi, const __nv_bfloat16* __restrict__ Blo,
    uint32_t sm_base, int stage, int row0, int col0, int kk, int K, int tid)
{
    const uint32_t st = sm_base + (uint32_t)stage * STAGE_E * 2;
#pragma unroll
    for (int u = 0; u < 2; u++) {
        int s  = tid + u * 256;
        int r  = s >> 2;
        int cg = (s & 3) * 8;
        size_t goffA = (size_t)(row0 + r) * K + kk + cg;
        size_t goffB = (size_t)(col0 + r) * K + kk + cg;
        uint32_t so = (uint32_t)(r * SPAD + cg) * 2;
        cp16(st + 0 * TILE_E * 2 + so, Ahi + goffA);
        cp16(st + 1 * TILE_E * 2 + so, Alo + goffA);
        cp16(st + 2 * TILE_E * 2 + so, Bhi + goffB);
        cp16(st + 3 * TILE_E * 2 + so, Blo + goffB);
    }
}

__global__ __launch_bounds__(256, 2)
void gemm_hmma_async(const __nv_bfloat16* __restrict__ Ahi,
                     const __nv_bfloat16* __restrict__ Alo,
                     const __nv_bfloat16* __restrict__ Bhi,
                     const __nv_bfloat16* __restrict__ Blo,
                     const float* __restrict__ bias,
                     float* __restrict__ C, int M, int N, int K)
{
    extern __shared__ __nv_bfloat16 sm[];
    const uint32_t sm_base = smem_u32(sm);

    const int tid  = threadIdx.x;
    const int lane = tid & 31;
    const int warp = tid >> 5;
    const int row0 = blockIdx.y * 128;
    const int col0 = blockIdx.x * 128;
    const int warp_m = (warp & 3) * 32;
    const int warp_n = (warp >> 2) * 64;

    float acc[2][8][4];
#pragma unroll
    for (int i = 0; i < 2; i++)
#pragma unroll
        for (int j = 0; j < 8; j++)
#pragma unroll
            for (int r = 0; r < 4; r++) acc[i][j][r] = 0.0f;

    const int a_r = warp_m + (lane & 15);
    const int a_c = (lane >> 4) * 8;
    const int b_r = warp_n + (lane & 7) + (lane >> 4) * 8;
    const int b_c = ((lane >> 3) & 1) * 8;

    const int nch = K >> 5;   // K / 32

    // prologue: chunk 0 -> stage 0
    gemm_issue_loads(Ahi, Alo, Bhi, Blo, sm_base, 0, row0, col0, 0, K, tid);
    CP_COMMIT();

    for (int c = 0; c < nch; c++) {
        const int cur = c & 1;
        if (c + 1 < nch) {
            gemm_issue_loads(Ahi, Alo, Bhi, Blo, sm_base, cur ^ 1,
                             row0, col0, (c + 1) << 5, K, tid);
            CP_COMMIT();
            CP_WAIT(1);
        } else {
            CP_WAIT(0);
        }
        __syncthreads();

        const __nv_bfloat16* sAhi = sm + cur * STAGE_E + 0 * TILE_E;
        const __nv_bfloat16* sAlo = sm + cur * STAGE_E + 1 * TILE_E;
        const __nv_bfloat16* sBhi = sm + cur * STAGE_E + 2 * TILE_E;
        const __nv_bfloat16* sBlo = sm + cur * STAGE_E + 3 * TILE_E;

#pragma unroll
        for (int ks = 0; ks < 32; ks += 16) {
            uint32_t a_h[2][4], a_l[2][4];
            uint32_t b_h[8][2], b_l[8][2];
#pragma unroll
            for (int i = 0; i < 2; i++) {
                int el = (a_r + i * 16) * SPAD + ks + a_c;
                ldm_x4(a_h[i], smem_u32(sAhi + el));
                ldm_x4(a_l[i], smem_u32(sAlo + el));
            }
#pragma unroll
            for (int jj = 0; jj < 4; jj++) {
                int el = (b_r + jj * 16) * SPAD + ks + b_c;
                ldm_x4(&b_h[jj * 2][0], smem_u32(sBhi + el));
                ldm_x4(&b_l[jj * 2][0], smem_u32(sBlo + el));
            }
            // pass-major: no back-to-back same-accumulator MMAs
#pragma unroll
            for (int i = 0; i < 2; i++)
#pragma unroll
                for (int j = 0; j < 8; j++)
                    mma_bf16(acc[i][j], a_h[i], b_h[j]);
#pragma unroll
            for (int i = 0; i < 2; i++)
#pragma unroll
                for (int j = 0; j < 8; j++)
                    mma_bf16(acc[i][j], a_h[i], b_l[j]);
#pragma unroll
            for (int i = 0; i < 2; i++)
#pragma unroll
                for (int j = 0; j < 8; j++)
                    mma_bf16(acc[i][j], a_l[i], b_h[j]);
        }
        __syncthreads();
    }

#pragma unroll
    for (int i = 0; i < 2; i++) {
#pragma unroll
        for (int j = 0; j < 8; j++) {
            int m = row0 + warp_m + i * 16 + (lane >> 2);
            int n = col0 + warp_n + j * 8 + (lane & 3) * 2;
            float2 bz = *reinterpret_cast<const float2*>(&bias[n]);
            float2 o0; o0.x = acc[i][j][0] + bz.x; o0.y = acc[i][j][1] + bz.y;
            float2 o1; o1.x = acc[i][j][2] + bz.x; o1.y = acc[i][j][3] + bz.y;
            *reinterpret_cast<float2*>(&C[(size_t)m * N + n]) = o0;
            *reinterpret_cast<float2*>(&C[(size_t)(m + 8) * N + n]) = o1;
        }
    }
}

// ===========================================================================
// Scores on HMMA: W[bh,q,k] = (Q.K)/8, masked. Lower-triangle tiles only.
// ===========================================================================
__global__ __launch_bounds__(256)
void scores_hmma_kernel(float* __restrict__ W)
{
    __shared__ __nv_bfloat16 sQ[2][128 * SPAD];
    __shared__ __nv_bfloat16 sK[2][128 * SPAD];

    const int tid  = threadIdx.x;
    const int lane = tid & 31;
    const int warp = tid >> 5;
    const int bh   = blockIdx.y;
    const int b    = bh >> 4;
    const int h    = bh & 15;

    int pair = blockIdx.x;
    int qt = (int)((-1.0f + sqrtf(1.0f + 8.0f * (float)pair)) * 0.5f);
    while ((qt + 1) * (qt + 2) / 2 <= pair) ++qt;
    while (qt * (qt + 1) / 2 > pair) --qt;
    const int kt = pair - qt * (qt + 1) / 2;

    const int q0 = qt * 128;
    const int k0 = kt * 128;
    const int warp_m = (warp & 3) * 32;
    const int warp_n = (warp >> 2) * 64;

    float acc[2][8][4];
#pragma unroll
    for (int i = 0; i < 2; i++)
#pragma unroll
        for (int j = 0; j < 8; j++)
#pragma unroll
            for (int r = 0; r < 4; r++) acc[i][j][r] = 0.0f;

    const int a_r = warp_m + (lane & 15);
    const int a_c = (lane >> 4) * 8;
    const int b_r = warp_n + (lane & 7) + (lane >> 4) * 8;
    const int b_c = ((lane >> 3) & 1) * 8;

    const size_t qbase = (size_t)(b * S_ + q0) * QKV_N + h * DH_;
    const size_t kbase = (size_t)(b * S_ + k0) * QKV_N + D_ + h * DH_;

    const int lr = tid >> 1;
    const int lc0 = (tid & 1) * 16;

    for (int dc = 0; dc < DH_; dc += 32) {
#pragma unroll
        for (int i = 0; i < 4; i++) {
            int c = lc0 + i * 4;
            float4 vq = *reinterpret_cast<const float4*>(
                &g_qkv[qbase + (size_t)lr * QKV_N + dc + c]);
            float4 vk = *reinterpret_cast<const float4*>(
                &g_qkv[kbase + (size_t)lr * QKV_N + dc + c]);
            split4(vq, &sQ[0][lr * SPAD + c], &sQ[1][lr * SPAD + c]);
            split4(vk, &sK[0][lr * SPAD + c], &sK[1][lr * SPAD + c]);
        }
        __syncthreads();

#pragma unroll
        for (int ks = 0; ks < 32; ks += 16) {
            uint32_t a_h[2][4], a_l[2][4];
            uint32_t b_h[8][2], b_l[8][2];
#pragma unroll
            for (int i = 0; i < 2; i++) {
                int el = (a_r + i * 16) * SPAD + ks + a_c;
                ldm_x4(a_h[i], smem_u32(&sQ[0][el]));
                ldm_x4(a_l[i], smem_u32(&sQ[1][el]));
            }
#pragma unroll
            for (int jj = 0; jj < 4; jj++) {
                int el = (b_r + jj * 16) * SPAD + ks + b_c;
                ldm_x4(&b_h[jj * 2][0], smem_u32(&sK[0][el]));
                ldm_x4(&b_l[jj * 2][0], smem_u32(&sK[1][el]));
            }
#pragma unroll
            for (int i = 0; i < 2; i++)
#pragma unroll
                for (int j = 0; j < 8; j++)
                    mma_bf16(acc[i][j], a_h[i], b_h[j]);
#pragma unroll
            for (int i = 0; i < 2; i++)
#pragma unroll
                for (int j = 0; j < 8; j++)
                    mma_bf16(acc[i][j], a_h[i], b_l[j]);
#pragma unroll
            for (int i = 0; i < 2; i++)
#pragma unroll
                for (int j = 0; j < 8; j++)
                    mma_bf16(acc[i][j], a_l[i], b_h[j]);
        }
        __syncthreads();
    }

    float* Wbh = W + (size_t)bh * S_ * S_;
#pragma unroll
    for (int i = 0; i < 2; i++) {
#pragma unroll
        for (int j = 0; j < 8; j++) {
            int q  = q0 + warp_m + i * 16 + (lane >> 2);
            int k  = k0 + warp_n + j * 8 + (lane & 3) * 2;
            float2 o0, o1;
            o0.x = (k     > q) ? MASKED_BIAS : acc[i][j][0] * 0.125f;
            o0.y = (k + 1 > q) ? MASKED_BIAS : acc[i][j][1] * 0.125f;
            o1.x = (k     > q + 8) ? MASKED_BIAS : acc[i][j][2] * 0.125f;
            o1.y = (k + 1 > q + 8) ? MASKED_BIAS : acc[i][j][3] * 0.125f;
            *reinterpret_cast<float2*>(&Wbh[(size_t)q * S_ + k]) = o0;
            *reinterpret_cast<float2*>(&Wbh[(size_t)(q + 8) * S_ + k]) = o1;
        }
    }
}

// ---------------------------------------------------------------------------
// Softmax in place: float4 IO, warp-shuffle reductions, __expf.
// ---------------------------------------------------------------------------
__global__ __launch_bounds__(256)
void softmax_kernel(float* __restrict__ W)
{
    const int tid = threadIdx.x;
    const int lane = tid & 31;
    const int warp = tid >> 5;
    const int row = blockIdx.x;
    const int q = row & (S_ - 1);
    const int nvalid = q + 1;
    float* w = W + (size_t)row * S_;

    __shared__ float red[8];

    float4 v[2];
    float m = -1e30f;
#pragma unroll
    for (int r = 0; r < 2; r++) {
        int k0 = (r * 256 + tid) * 4;
        float4 x = *reinterpret_cast<const float4*>(w + k0);
        x.x = (k0 + 0 < nvalid) ? x.x : -1e30f;
        x.y = (k0 + 1 < nvalid) ? x.y : -1e30f;
        x.z = (k0 + 2 < nvalid) ? x.z : -1e30f;
        x.w = (k0 + 3 < nvalid) ? x.w : -1e30f;
        v[r] = x;
        m = fmaxf(m, fmaxf(fmaxf(x.x, x.y), fmaxf(x.z, x.w)));
    }
#pragma unroll
    for (int off = 16; off > 0; off >>= 1)
        m = fmaxf(m, __shfl_xor_sync(0xFFFFFFFFu, m, off));
    if (lane == 0) red[warp] = m;
    __syncthreads();
    float mx = red[0];
#pragma unroll
    for (int i = 1; i < 8; i++) mx = fmaxf(mx, red[i]);
    __syncthreads();

    float s = 0.0f;
#pragma unroll
    for (int r = 0; r < 2; r++) {
        int k0 = (r * 256 + tid) * 4;
        float4 x = v[r];
        x.x = (k0 + 0 < nvalid) ? __expf(x.x - mx) : 0.0f;
        x.y = (k0 + 1 < nvalid) ? __expf(x.y - mx) : 0.0f;
        x.z = (k0 + 2 < nvalid) ? __expf(x.z - mx) : 0.0f;
        x.w = (k0 + 3 < nvalid) ? __expf(x.w - mx) : 0.0f;
        v[r] = x;
        s += x.x + x.y + x.z + x.w;
    }
#pragma unroll
    for (int off = 16; off > 0; off >>= 1)
        s += __shfl_xor_sync(0xFFFFFFFFu, s, off);
    if (lane == 0) red[warp] = s;
    __syncthreads();
    float tot = red[0];
#pragma unroll
    for (int i = 1; i < 8; i++) tot += red[i];
    const float inv = 1.0f / tot;

#pragma unroll
    for (int r = 0; r < 2; r++) {
        int k0 = (r * 256 + tid) * 4;
        float4 x = v[r];
        x.x *= inv; x.y *= inv; x.z *= inv; x.w *= inv;
        *reinterpret_cast<float4*>(w + k0) = x;
    }
}

// ===========================================================================
// AV on HMMA: g_attn = softmax(W) @ V. Causal chunk range.
// ===========================================================================
__global__ __launch_bounds__(256)
void av_hmma_kernel(const float* __restrict__ W)
{
    __shared__ __nv_bfloat16 sW[2][128 * SPAD];
    __shared__ __nv_bfloat16 sV[2][64 * SPAD];

    const int tid  = threadIdx.x;
    const int lane = tid & 31;
    const int warp = tid >> 5;
    const int bh   = blockIdx.y;
    const int b    = bh >> 4;
    const int h    = bh & 15;
    const int q0   = blockIdx.x * 128;
    const int warp_m = warp * 16;

    const float* Wbh = W + (size_t)bh * S_ * S_;
    const size_t vbase = (size_t)b * S_ * QKV_N + 2 * D_ + h * DH_;

    float acc[8][4];
#pragma unroll
    for (int j = 0; j < 8; j++)
#pragma unroll
        for (int r = 0; r < 4; r++) acc[j][r] = 0.0f;

    const int a_r = warp_m + (lane & 15);
    const int a_c = (lane >> 4) * 8;
    const int b_r = (lane & 7) + (lane >> 4) * 8;
    const int b_c = ((lane >> 3) & 1) * 8;

    const int wr  = tid >> 1;
    const int wc0 = (tid & 1) * 16;
    const int vd  = tid & 63;
    const int vk0 = (tid >> 6) * 8;

    const int nch = (blockIdx.x + 1) * 4;
    for (int t = 0; t < nch; t++) {
        const int kc = t * 32;
#pragma unroll
        for (int i = 0; i < 4; i++) {
            int c = wc0 + i * 4;
            float4 v = *reinterpret_cast<const float4*>(
                &Wbh[(size_t)(q0 + wr) * S_ + kc + c]);
            split4(v, &sW[0][wr * SPAD + c], &sW[1][wr * SPAD + c]);
        }
        {
            uint32_t hp[4], lp[4];
#pragma unroll
            for (int i = 0; i < 4; i++) {
                float x0 = g_qkv[vbase + (size_t)(kc + vk0 + 2 * i) * QKV_N + vd];
                float x1 = g_qkv[vbase + (size_t)(kc + vk0 + 2 * i + 1) * QKV_N + vd];
                __nv_bfloat162 hh, ll;
                hh.x = __float2bfloat16(x0); hh.y = __float2bfloat16(x1);
                ll.x = __float2bfloat16(x0 - __bfloat162float(hh.x));
                ll.y = __float2bfloat16(x1 - __bfloat162float(hh.y));
                hp[i] = *reinterpret_cast<uint32_t*>(&hh);
                lp[i] = *reinterpret_cast<uint32_t*>(&ll);
            }
            uint4 hv; hv.x = hp[0]; hv.y = hp[1]; hv.z = hp[2]; hv.w = hp[3];
            uint4 lv; lv.x = lp[0]; lv.y = lp[1]; lv.z = lp[2]; lv.w = lp[3];
            *reinterpret_cast<uint4*>(&sV[0][vd * SPAD + vk0]) = hv;
            *reinterpret_cast<uint4*>(&sV[1][vd * SPAD + vk0]) = lv;
        }
        __syncthreads();

#pragma unroll
        for (int ks = 0; ks < 32; ks += 16) {
            uint32_t a_h[4], a_l[4];
            uint32_t b_h[8][2], b_l[8][2];
            {
                int el = a_r * SPAD + ks + a_c;
                ldm_x4(a_h, smem_u32(&sW[0][el]));
                ldm_x4(a_l, smem_u32(&sW[1][el]));
            }
#pragma unroll
            for (int jj = 0; jj < 4; jj++) {
                int el = (b_r + jj * 16) * SPAD + ks + b_c;
                ldm_x4(&b_h[jj * 2][0], smem_u32(&sV[0][el]));
                ldm_x4(&b_l[jj * 2][0], smem_u32(&sV[1][el]));
            }
#pragma unroll
            for (int j = 0; j < 8; j++)
                mma_bf16(acc[j], a_h, b_h[j]);
#pragma unroll
            for (int j = 0; j < 8; j++)
                mma_bf16(acc[j], a_h, b_l[j]);
#pragma unroll
            for (int j = 0; j < 8; j++)
                mma_bf16(acc[j], a_l, b_h[j]);
        }
        __syncthreads();
    }

#pragma unroll
    for (int j = 0; j < 8; j++) {
        int m = q0 + warp_m + (lane >> 2);
        int n = j * 8 + (lane & 3) * 2;
        float2 o0; o0.x = acc[j][0]; o0.y = acc[j][1];
        float2 o1; o1.x = acc[j][2]; o1.y = acc[j][3];
        *reinterpret_cast<float2*>(
            &g_attn[(size_t)(b * S_ + m) * D_ + h * DH_ + n]) = o0;
        *reinterpret_cast<float2*>(
            &g_attn[(size_t)(b * S_ + m + 8) * D_ + h * DH_ + n]) = o1;
    }
}

// ---------------------------------------------------------------------------
extern "C" void kernel_launch(void* const* d_in, const int* in_sizes, int n_in,
                              void* d_out, int out_size)
{
    const float* hs       = (const float*)d_in[0];  // [2,2048,1024]
    const float* c_attn_w = (const float*)d_in[1];  // [1024,3072]
    const float* c_attn_b = (const float*)d_in[2];  // [3072]
    const float* c_proj_w = (const float*)d_in[3];  // [1024,1024]
    const float* c_proj_b = (const float*)d_in[4];  // [1024]

    float* out  = (float*)d_out;
    float* Wout = out + OUT_ATTN_ELEMS;

    float *qkv_ptr = nullptr, *attn_ptr = nullptr;
    __nv_bfloat16 *ahi, *alo, *w1hi, *w1lo, *w2hi, *w2lo;
    cudaGetSymbolAddress((void**)&qkv_ptr, g_qkv);
    cudaGetSymbolAddress((void**)&attn_ptr, g_attn);
    cudaGetSymbolAddress((void**)&ahi,  g_ahi);
    cudaGetSymbolAddress((void**)&alo,  g_alo);
    cudaGetSymbolAddress((void**)&w1hi, g_w1hi);
    cudaGetSymbolAddress((void**)&w1lo, g_w1lo);
    cudaGetSymbolAddress((void**)&w2hi, g_w2hi);
    cudaGetSymbolAddress((void**)&w2lo, g_w2lo);

    static bool attr_set = false;
    if (!attr_set) {
        cudaFuncSetAttribute(gemm_hmma_async,
                             cudaFuncAttributeMaxDynamicSharedMemorySize,
                             GEMM_SMEM_BYTES);
        attr_set = true;
    }

    // 0) splits for dense GEMMs
    split_rows_kernel<<<(BS_ * D_ / 4 + 255) / 256, 256>>>(hs, ahi, alo, BS_ * D_ / 4);
    split_T_kernel<<<dim3(QKV_N / 32, D_ / 32), 256>>>(c_attn_w, w1hi, w1lo, D_, QKV_N);
    split_T_kernel<<<dim3(D_ / 32, D_ / 32), 256>>>(c_proj_w, w2hi, w2lo, D_, D_);

    // 1) QKV GEMM (HMMA, cp.async pipelined)
    gemm_hmma_async<<<dim3(QKV_N / 128, BS_ / 128), 256, GEMM_SMEM_BYTES>>>(
        ahi, alo, w1hi, w1lo, c_attn_b, qkv_ptr, BS_, QKV_N, D_);

    // 2) Scores (HMMA, lower-triangle tiles only)
    scores_hmma_kernel<<<dim3(136, B_ * H_), 256>>>(Wout);

    // 3) Softmax in place
    softmax_kernel<<<B_ * H_ * S_, 256>>>(Wout);

    // 4) AV (HMMA) -> g_attn
    av_hmma_kernel<<<dim3(S_ / 128, B_ * H_), 256>>>(Wout);

    // 5) split attn output, then proj GEMM (HMMA, pipelined)
    split_rows_kernel<<<(BS_ * D_ / 4 + 255) / 256, 256>>>(attn_ptr, ahi, alo, BS_ * D_ / 4);
    gemm_hmma_async<<<dim3(D_ / 128, BS_ / 128), 256, GEMM_SMEM_BYTES>>>(
        ahi, alo, w2hi, w2lo, c_proj_b, out, BS_, D_, D_);
}